// round 1
// baseline (speedup 1.0000x reference)
#include <cuda_runtime.h>
#include <cuda_bf16.h>
#include <math.h>

// ---------------- problem constants ----------------
#define BB   2
#define SS   2048
#define EE   512
#define HH   8
#define LL   4
#define DHH  64
#define MMF  128          // FAVOR random features
#define AAX  3
#define NVOC 17           // VOCAB+1
#define BHH  (BB*HH)      // 16
#define BSR  (BB*SS)      // 4096 rows
#define NCH  (SS/128)     // 16 chunks of 128
#define FFD  (4*EE)       // 2048

#define DNQ   0.3535533905932738f     // 64^-0.25
#define RATIO 0.08838834764831845f    // 128^-0.5
#define KEPS  1e-4f
#define DEPS  1e-6f

// ---------------- scratch (static device globals; no allocation) ----------------
__device__ float g_x [BSR*EE];
__device__ float g_h [BSR*EE];
__device__ float g_q [BSR*EE];
__device__ float g_k [BSR*EE];
__device__ float g_v [BSR*EE];
__device__ float g_o [BSR*EE];
__device__ float g_ff[BSR*FFD];
__device__ float g_qp[BHH*SS*MMF];
__device__ float g_kp[BHH*SS*MMF];
__device__ float g_kdiag[BHH*SS];
__device__ unsigned g_kmax;
__device__ float g_Sc[BHH*NCH*MMF*DHH];
__device__ float g_Sp[BHH*NCH*MMF*DHH];
__device__ float g_zc[BHH*NCH*MMF];
__device__ float g_zp[BHH*NCH*MMF];
__device__ float g_P [BHH*NCH*128*128];

// ---------------- helpers ----------------
__device__ __forceinline__ unsigned f_enc(float f){
    unsigned u = __float_as_uint(f);
    return (u & 0x80000000u) ? ~u : (u | 0x80000000u);
}
__device__ __forceinline__ float f_dec(unsigned u){
    return (u & 0x80000000u) ? __uint_as_float(u & 0x7fffffffu) : __uint_as_float(~u);
}

// ---------------- embedding + right-shift with SOS ----------------
__global__ void embed_kernel(const int* __restrict__ value, const int* __restrict__ depth,
                             const int* __restrict__ pos,   const float* __restrict__ sos,
                             const float* __restrict__ tok, const float* __restrict__ dep,
                             const float* __restrict__ spa)
{
    int i = blockIdx.x * 256 + threadIdx.x;
    if (i >= BSR*EE) return;
    int e = i & (EE-1);
    int r = i >> 9;            // row = b*S + s
    int b = r / SS, s = r - b*SS;
    float val;
    if (s == 0) {
        val = sos[e];
    } else {
        int p = b*SS + s - 1;
        val = tok[value[p]*EE + e] + dep[depth[p]*EE + e];
        #pragma unroll
        for (int a = 0; a < AAX; a++)
            val += spa[(size_t)a*65*EE + pos[p*AAX + a]*EE + e];
    }
    g_x[i] = val;
}

// ---------------- layernorm (row = 512) ----------------
__global__ __launch_bounds__(128) void ln_kernel(const float* __restrict__ in, float* __restrict__ out,
                                                 const float* __restrict__ w, const float* __restrict__ bia)
{
    int r = blockIdx.x, t = threadIdx.x;
    const float4 v = ((const float4*)(in + (size_t)r*EE))[t];
    float s  = v.x + v.y + v.z + v.w;
    float sq = v.x*v.x + v.y*v.y + v.z*v.z + v.w*v.w;
    #pragma unroll
    for (int o = 16; o; o >>= 1){ s += __shfl_xor_sync(~0u, s, o); sq += __shfl_xor_sync(~0u, sq, o); }
    __shared__ float sh[8];
    if ((t & 31) == 0){ sh[t>>5] = s; sh[4 + (t>>5)] = sq; }
    __syncthreads();
    s  = sh[0]+sh[1]+sh[2]+sh[3];
    sq = sh[4]+sh[5]+sh[6]+sh[7];
    float mu  = s * (1.f/EE);
    float var = sq * (1.f/EE) - mu*mu;
    float rs  = rsqrtf(var + 1e-5f);
    float4 wv = ((const float4*)w)[t], bv = ((const float4*)bia)[t];
    float4 o4;
    o4.x = (v.x-mu)*rs*wv.x + bv.x;
    o4.y = (v.y-mu)*rs*wv.y + bv.y;
    o4.z = (v.z-mu)*rs*wv.z + bv.z;
    o4.w = (v.w-mu)*rs*wv.w + bv.w;
    ((float4*)(out + (size_t)r*EE))[t] = o4;
}

// ---------------- SGEMM: C[M,N] = A[M,K]@B[K,N] + bias (+gelu) (+resid) ----------------
__global__ __launch_bounds__(256) void sgemm_kernel(
    const float* __restrict__ Am, const float* __restrict__ Bm,
    const float* __restrict__ bias, const float* __restrict__ resid,
    float* __restrict__ C, int N, int K, int act)
{
    __shared__ float As[8][128];
    __shared__ float Bs[8][128];
    const int tid = threadIdx.x;
    const int bm = blockIdx.y * 128, bn = blockIdx.x * 128;
    const int ty = tid >> 4, tx = tid & 15;
    float acc[8][8];
    #pragma unroll
    for (int i = 0; i < 8; i++)
        #pragma unroll
        for (int j = 0; j < 8; j++) acc[i][j] = 0.f;

    const int arow = tid >> 1, ak = (tid & 1) << 2;
    const int brow = tid >> 5, bcol = (tid & 31) << 2;
    const float* Aptr = Am + (size_t)(bm + arow)*K + ak;
    const float* Bptr = Bm + (size_t)brow*N + bn + bcol;

    for (int k0 = 0; k0 < K; k0 += 8){
        float4 a4 = *(const float4*)Aptr;
        As[ak+0][arow] = a4.x; As[ak+1][arow] = a4.y;
        As[ak+2][arow] = a4.z; As[ak+3][arow] = a4.w;
        *(float4*)&Bs[brow][bcol] = *(const float4*)Bptr;
        __syncthreads();
        #pragma unroll
        for (int kk = 0; kk < 8; kk++){
            float a[8], b[8];
            *(float4*)(a  ) = *(const float4*)&As[kk][ty*8];
            *(float4*)(a+4) = *(const float4*)&As[kk][ty*8+4];
            *(float4*)(b  ) = *(const float4*)&Bs[kk][tx*8];
            *(float4*)(b+4) = *(const float4*)&Bs[kk][tx*8+4];
            #pragma unroll
            for (int i = 0; i < 8; i++)
                #pragma unroll
                for (int j = 0; j < 8; j++) acc[i][j] += a[i]*b[j];
        }
        __syncthreads();
        Aptr += 8;
        Bptr += (size_t)8*N;
    }
    #pragma unroll
    for (int i = 0; i < 8; i++){
        int r = bm + ty*8 + i;
        #pragma unroll
        for (int j = 0; j < 8; j++){
            int c = bn + tx*8 + j;
            float v = acc[i][j] + bias[c];
            if (act) v = 0.5f * v * (1.f + erff(v * 0.70710678118654752f));
            if (resid) v += resid[(size_t)r*N + c];
            C[(size_t)r*N + c] = v;
        }
    }
}

// ---------------- FAVOR+ query features ----------------
__global__ __launch_bounds__(128) void qfeat_kernel(const float* __restrict__ proj)
{
    __shared__ float pr[MMF][DHH+1];
    __shared__ float xd[DHH];
    __shared__ float red[8];
    const int t = threadIdx.x;
    for (int i = t; i < MMF*DHH; i += 128) pr[i>>6][i&63] = proj[i];
    const int bh = blockIdx.y;
    const int b = bh / HH, h = bh % HH;
    const int s0 = blockIdx.x * 32;
    for (int rr = 0; rr < 32; rr++){
        int s = s0 + rr;
        float sq = 0.f;
        if (t < DHH){
            float vv = g_q[(size_t)(b*SS + s)*EE + h*DHH + t] * DNQ;
            xd[t] = vv; sq = vv*vv;
        }
        #pragma unroll
        for (int o = 16; o; o >>= 1) sq += __shfl_xor_sync(~0u, sq, o);
        if ((t & 31) == 0) red[t>>5] = sq;
        __syncthreads();
        float diag = 0.5f * (red[0] + red[1]);
        float dd = 0.f;
        #pragma unroll
        for (int d = 0; d < DHH; d++) dd += xd[d] * pr[t][d];
        float mx = dd;
        #pragma unroll
        for (int o = 16; o; o >>= 1) mx = fmaxf(mx, __shfl_xor_sync(~0u, mx, o));
        if ((t & 31) == 0) red[4 + (t>>5)] = mx;
        __syncthreads();
        mx = fmaxf(fmaxf(red[4], red[5]), fmaxf(red[6], red[7]));
        g_qp[((size_t)bh*SS + s)*MMF + t] = RATIO * (expf(dd - diag - mx) + KEPS);
    }
}

// ---------------- key features: pass 1 (raw dd, diag, global max) ----------------
__global__ void reset_kmax_kernel(){ g_kmax = 0u; }

__global__ __launch_bounds__(128) void kfeat1_kernel(const float* __restrict__ proj)
{
    __shared__ float pr[MMF][DHH+1];
    __shared__ float xd[DHH];
    __shared__ float red[8];
    const int t = threadIdx.x;
    for (int i = t; i < MMF*DHH; i += 128) pr[i>>6][i&63] = proj[i];
    const int bh = blockIdx.y;
    const int b = bh / HH, h = bh % HH;
    const int s0 = blockIdx.x * 32;
    float runmax = -3.4e38f;
    for (int rr = 0; rr < 32; rr++){
        int s = s0 + rr;
        float sq = 0.f;
        if (t < DHH){
            float vv = g_k[(size_t)(b*SS + s)*EE + h*DHH + t] * DNQ;
            xd[t] = vv; sq = vv*vv;
        }
        #pragma unroll
        for (int o = 16; o; o >>= 1) sq += __shfl_xor_sync(~0u, sq, o);
        if ((t & 31) == 0) red[t>>5] = sq;
        __syncthreads();
        float diag = 0.5f * (red[0] + red[1]);
        float dd = 0.f;
        #pragma unroll
        for (int d = 0; d < DHH; d++) dd += xd[d] * pr[t][d];
        g_kp[((size_t)bh*SS + s)*MMF + t] = dd;
        if (t == 0) g_kdiag[bh*SS + s] = diag;
        runmax = fmaxf(runmax, dd);
        __syncthreads();
    }
    #pragma unroll
    for (int o = 16; o; o >>= 1) runmax = fmaxf(runmax, __shfl_xor_sync(~0u, runmax, o));
    if ((t & 31) == 0) red[4 + (t>>5)] = runmax;
    __syncthreads();
    if (t == 0){
        float m = fmaxf(fmaxf(red[4], red[5]), fmaxf(red[6], red[7]));
        atomicMax(&g_kmax, f_enc(m));
    }
}

// ---------------- key features: pass 2 (exp) ----------------
__global__ __launch_bounds__(512) void kfeat2_kernel()
{
    int i = blockIdx.x * 512 + threadIdx.x;
    float gm = f_dec(g_kmax);
    g_kp[i] = RATIO * (expf(g_kp[i] - g_kdiag[i >> 7] - gm) + KEPS);
}

// ---------------- per-chunk KV state: Sc[m,d], zc[m] ----------------
__global__ __launch_bounds__(256) void chunk_kv_kernel()
{
    const int c = blockIdx.x, bh = blockIdx.y;
    const int b = bh / HH, h = bh % HH;
    __shared__ float Kt[16][128];
    __shared__ float Vt[16][64];
    const int tid = threadIdx.x;
    const int ty = tid >> 4, tx = tid & 15;
    float acc[8][4]; float zacc[8];
    #pragma unroll
    for (int i = 0; i < 8; i++){ zacc[i] = 0.f;
        #pragma unroll
        for (int j = 0; j < 4; j++) acc[i][j] = 0.f; }

    for (int t0 = 0; t0 < 128; t0 += 16){
        #pragma unroll
        for (int i = 0; i < 2; i++){
            int f = tid + i*256;
            *(float4*)&Kt[f>>5][(f&31)<<2] =
                *(const float4*)&g_kp[((size_t)bh*SS + c*128 + t0 + (f>>5))*MMF + ((f&31)<<2)];
        }
        *(float4*)&Vt[tid>>4][(tid&15)<<2] =
            *(const float4*)&g_v[((size_t)(b*SS + c*128 + t0 + (tid>>4)))*EE + h*DHH + ((tid&15)<<2)];
        __syncthreads();
        #pragma unroll
        for (int tt = 0; tt < 16; tt++){
            float a[8], bv[4];
            *(float4*)(a  ) = *(const float4*)&Kt[tt][ty*8];
            *(float4*)(a+4) = *(const float4*)&Kt[tt][ty*8+4];
            *(float4*)(bv ) = *(const float4*)&Vt[tt][tx*4];
            #pragma unroll
            for (int i = 0; i < 8; i++){
                #pragma unroll
                for (int j = 0; j < 4; j++) acc[i][j] += a[i]*bv[j];
                if (tx == 0) zacc[i] += a[i];
            }
        }
        __syncthreads();
    }
    size_t base = ((size_t)(bh*NCH + c))*MMF;
    #pragma unroll
    for (int i = 0; i < 8; i++){
        int m = ty*8 + i;
        #pragma unroll
        for (int j = 0; j < 4; j++)
            g_Sc[(base + m)*DHH + tx*4 + j] = acc[i][j];
        if (tx == 0) g_zc[base + m] = zacc[i];
    }
}

// ---------------- exclusive prefix over chunks ----------------
__global__ __launch_bounds__(512) void chunk_prefix_kernel()
{
    const int bh = blockIdx.x, t = threadIdx.x;
    float run[16];
    #pragma unroll
    for (int j = 0; j < 16; j++) run[j] = 0.f;
    float rz = 0.f;
    for (int c = 0; c < NCH; c++){
        size_t base = ((size_t)(bh*NCH + c))*MMF*DHH;
        #pragma unroll
        for (int j = 0; j < 16; j++){
            int idx = t + j*512;
            g_Sp[base + idx] = run[j];
            run[j] += g_Sc[base + idx];
        }
        if (t < MMF){
            int zb = (bh*NCH + c)*MMF + t;
            g_zp[zb] = rz;
            rz += g_zc[zb];
        }
    }
}

// ---------------- intra-chunk P = mask(Q K^T) ----------------
__global__ __launch_bounds__(256) void chunk_p_kernel()
{
    const int c = blockIdx.x, bh = blockIdx.y;
    __shared__ float Qs[16][128];
    __shared__ float Ks[16][128];
    const int tid = threadIdx.x;
    const int ty = tid >> 4, tx = tid & 15;
    float acc[8][8];
    #pragma unroll
    for (int i = 0; i < 8; i++)
        #pragma unroll
        for (int j = 0; j < 8; j++) acc[i][j] = 0.f;

    const size_t rowbase = (size_t)bh*SS + c*128;
    for (int m0 = 0; m0 < 128; m0 += 16){
        #pragma unroll
        for (int i = 0; i < 2; i++){
            int f = tid + i*256;
            int trow = f >> 2, mq = (f & 3) << 2;
            float4 qv = *(const float4*)&g_qp[(rowbase + trow)*MMF + m0 + mq];
            Qs[mq+0][trow] = qv.x; Qs[mq+1][trow] = qv.y; Qs[mq+2][trow] = qv.z; Qs[mq+3][trow] = qv.w;
            float4 kv = *(const float4*)&g_kp[(rowbase + trow)*MMF + m0 + mq];
            Ks[mq+0][trow] = kv.x; Ks[mq+1][trow] = kv.y; Ks[mq+2][trow] = kv.z; Ks[mq+3][trow] = kv.w;
        }
        __syncthreads();
        #pragma unroll
        for (int mm = 0; mm < 16; mm++){
            float a[8], b[8];
            *(float4*)(a  ) = *(const float4*)&Qs[mm][ty*8];
            *(float4*)(a+4) = *(const float4*)&Qs[mm][ty*8+4];
            *(float4*)(b  ) = *(const float4*)&Ks[mm][tx*8];
            *(float4*)(b+4) = *(const float4*)&Ks[mm][tx*8+4];
            #pragma unroll
            for (int i = 0; i < 8; i++)
                #pragma unroll
                for (int j = 0; j < 8; j++) acc[i][j] += a[i]*b[j];
        }
        __syncthreads();
    }
    size_t pbase = ((size_t)(bh*NCH + c))*128;
    #pragma unroll
    for (int i = 0; i < 8; i++){
        int r = ty*8 + i;
        #pragma unroll
        for (int j = 0; j < 8; j++){
            int cc = tx*8 + j;
            g_P[(pbase + r)*128 + cc] = (cc <= r) ? acc[i][j] : 0.f;
        }
    }
}

// ---------------- out = ([P|Q] @ [v;1 | Sp;zp]) with fused denominator ----------------
__global__ __launch_bounds__(256) void chunk_o_kernel()
{
    const int c = blockIdx.x, bh = blockIdx.y;
    const int b = bh / HH, h = bh % HH;
    __shared__ float Gs[16][128];
    __shared__ float Hs[16][64];
    __shared__ float h2s[16];
    __shared__ float densh[128];
    const int tid = threadIdx.x;
    const int ty = tid >> 4, tx = tid & 15;
    float acc[8][4]; float den[8];
    #pragma unroll
    for (int i = 0; i < 8; i++){ den[i] = 0.f;
        #pragma unroll
        for (int j = 0; j < 4; j++) acc[i][j] = 0.f; }

    const size_t pbase = ((size_t)(bh*NCH + c))*128;
    const size_t qbase = (size_t)bh*SS + c*128;
    const size_t sbase = ((size_t)(bh*NCH + c))*MMF;

    for (int j0 = 0; j0 < 256; j0 += 16){
        #pragma unroll
        for (int i = 0; i < 2; i++){
            int f = tid + i*256;
            int trow = f >> 2, jq = (f & 3) << 2;
            float4 gv;
            if (j0 < 128)
                gv = *(const float4*)&g_P[(pbase + trow)*128 + j0 + jq];
            else
                gv = *(const float4*)&g_qp[(qbase + trow)*MMF + (j0 - 128) + jq];
            Gs[jq+0][trow] = gv.x; Gs[jq+1][trow] = gv.y; Gs[jq+2][trow] = gv.z; Gs[jq+3][trow] = gv.w;
        }
        {
            int jrow = tid >> 4, d4 = (tid & 15) << 2;
            float4 hv;
            if (j0 < 128)
                hv = *(const float4*)&g_v[((size_t)(b*SS + c*128 + j0 + jrow))*EE + h*DHH + d4];
            else
                hv = *(const float4*)&g_Sp[(sbase + (j0 - 128 + jrow))*DHH + d4];
            *(float4*)&Hs[jrow][d4] = hv;
        }
        if (tid < 16) h2s[tid] = (j0 < 128) ? 1.f : g_zp[sbase + (j0 - 128) + tid];
        __syncthreads();
        #pragma unroll
        for (int jj = 0; jj < 16; jj++){
            float a[8], bv[4];
            *(float4*)(a  ) = *(const float4*)&Gs[jj][ty*8];
            *(float4*)(a+4) = *(const float4*)&Gs[jj][ty*8+4];
            *(float4*)(bv ) = *(const float4*)&Hs[jj][tx*4];
            #pragma unroll
            for (int i = 0; i < 8; i++){
                #pragma unroll
                for (int j = 0; j < 4; j++) acc[i][j] += a[i]*bv[j];
                if (tx == 0) den[i] += a[i]*h2s[jj];
            }
        }
        __syncthreads();
    }
    if (tx == 0)
        #pragma unroll
        for (int i = 0; i < 8; i++) densh[ty*8 + i] = den[i];
    __syncthreads();
    #pragma unroll
    for (int i = 0; i < 8; i++){
        int r = ty*8 + i;
        float dinv = 1.f / (densh[r] + DEPS);
        #pragma unroll
        for (int j = 0; j < 4; j++)
            g_o[((size_t)(b*SS + c*128 + r))*EE + h*DHH + tx*4 + j] = acc[i][j]*dinv;
    }
}

// ---------------- head projection ----------------
__global__ __launch_bounds__(64) void head_kernel(const float* __restrict__ hw, float* __restrict__ out)
{
    __shared__ float xs[EE];
    const int r = blockIdx.x, t = threadIdx.x;
    ((float4*)xs)[t]      = ((const float4*)(g_x + (size_t)r*EE))[t];
    ((float4*)xs)[t + 64] = ((const float4*)(g_x + (size_t)r*EE))[t + 64];
    __syncthreads();
    if (t < NVOC){
        float acc = 0.f;
        #pragma unroll 8
        for (int k = 0; k < EE; k++) acc += xs[k] * hw[k*NVOC + t];
        out[(size_t)r*NVOC + t] = acc;
    }
}

// ---------------- host launch ----------------
extern "C" void kernel_launch(void* const* d_in, const int* in_sizes, int n_in,
                              void* d_out, int out_size)
{
    (void)in_sizes; (void)n_in; (void)out_size;
    const int*   value = (const int*)  d_in[0];
    const int*   depth = (const int*)  d_in[1];
    const int*   pos   = (const int*)  d_in[2];
    const float* proj  = (const float*)d_in[3];
    const float* sos   = (const float*)d_in[4];
    const float* tok   = (const float*)d_in[5];
    const float* dep   = (const float*)d_in[6];
    const float* spa   = (const float*)d_in[7];
    const float* ln1w  = (const float*)d_in[8];
    const float* ln1b  = (const float*)d_in[9];
    const float* Wq    = (const float*)d_in[10];
    const float* bq    = (const float*)d_in[11];
    const float* Wk    = (const float*)d_in[12];
    const float* bk    = (const float*)d_in[13];
    const float* Wv    = (const float*)d_in[14];
    const float* bv    = (const float*)d_in[15];
    const float* Wo    = (const float*)d_in[16];
    const float* bo    = (const float*)d_in[17];
    const float* ln2w  = (const float*)d_in[18];
    const float* ln2b  = (const float*)d_in[19];
    const float* W1    = (const float*)d_in[20];
    const float* b1    = (const float*)d_in[21];
    const float* W2    = (const float*)d_in[22];
    const float* b2    = (const float*)d_in[23];
    const float* hw    = (const float*)d_in[24];

    float *px, *ph, *pq, *pk, *pv, *po, *pff;
    cudaGetSymbolAddress((void**)&px,  g_x);
    cudaGetSymbolAddress((void**)&ph,  g_h);
    cudaGetSymbolAddress((void**)&pq,  g_q);
    cudaGetSymbolAddress((void**)&pk,  g_k);
    cudaGetSymbolAddress((void**)&pv,  g_v);
    cudaGetSymbolAddress((void**)&po,  g_o);
    cudaGetSymbolAddress((void**)&pff, g_ff);

    embed_kernel<<<(BSR*EE + 255)/256, 256>>>(value, depth, pos, sos, tok, dep, spa);

    dim3 g512(4, 32);        // N=512 GEMMs
    dim3 g2048(16, 32);      // N=2048 GEMM
    dim3 gfeat(SS/32, BHH);
    dim3 gchunk(NCH, BHH);

    for (int l = 0; l < LL; l++){
        const float* prj = proj + (size_t)l*MMF*DHH;
        ln_kernel<<<BSR, 128>>>(px, ph, ln1w + l*EE, ln1b + l*EE);
        sgemm_kernel<<<g512, 256>>>(ph, Wq + (size_t)l*EE*EE, bq + l*EE, nullptr, pq, EE, EE, 0);
        sgemm_kernel<<<g512, 256>>>(ph, Wk + (size_t)l*EE*EE, bk + l*EE, nullptr, pk, EE, EE, 0);
        sgemm_kernel<<<g512, 256>>>(ph, Wv + (size_t)l*EE*EE, bv + l*EE, nullptr, pv, EE, EE, 0);

        qfeat_kernel<<<gfeat, 128>>>(prj);
        reset_kmax_kernel<<<1, 1>>>();
        kfeat1_kernel<<<gfeat, 128>>>(prj);
        kfeat2_kernel<<<(BHH*SS*MMF)/512, 512>>>();

        chunk_kv_kernel<<<gchunk, 256>>>();
        chunk_prefix_kernel<<<BHH, 512>>>();
        chunk_p_kernel<<<gchunk, 256>>>();
        chunk_o_kernel<<<gchunk, 256>>>();

        sgemm_kernel<<<g512, 256>>>(po, Wo + (size_t)l*EE*EE, bo + l*EE, px, px, EE, EE, 0);
        ln_kernel<<<BSR, 128>>>(px, ph, ln2w + l*EE, ln2b + l*EE);
        sgemm_kernel<<<g2048, 256>>>(ph, W1 + (size_t)l*EE*FFD, b1 + l*FFD, nullptr, pff, FFD, EE, 1);
        sgemm_kernel<<<g512, 256>>>(pff, W2 + (size_t)l*FFD*EE, b2 + l*EE, px, px, EE, FFD, 0);
    }

    head_kernel<<<BSR, 64>>>(hw, (float*)d_out);
}

// round 2
// speedup vs baseline: 2.1410x; 2.1410x over previous
#include <cuda_runtime.h>
#include <cuda_bf16.h>
#include <math.h>

// ---------------- problem constants ----------------
#define BB   2
#define SS   2048
#define EE   512
#define HH   8
#define LL   4
#define DHH  64
#define MMF  128          // FAVOR random features
#define AAX  3
#define NVOC 17           // VOCAB+1
#define BHH  (BB*HH)      // 16
#define BSR  (BB*SS)      // 4096 rows
#define NCH  (SS/128)     // 16 chunks of 128
#define FFD  (4*EE)       // 2048

#define DNQ   0.3535533905932738f     // 64^-0.25
#define RATIO 0.08838834764831845f    // 128^-0.5
#define KEPS  1e-4f
#define DEPS  1e-6f

// ---------------- scratch (static device globals; no allocation) ----------------
__device__ float g_x [BSR*EE];
__device__ float g_h [BSR*EE];
__device__ float g_q [BSR*EE];
__device__ float g_k [BSR*EE];
__device__ float g_v [BSR*EE];
__device__ float g_o [BSR*EE];
__device__ float g_ff[BSR*FFD];
__device__ float g_qp[BHH*SS*MMF];
__device__ float g_kp[BHH*SS*MMF];
__device__ float g_kdiag[BHH*SS];
__device__ unsigned g_kmax;
__device__ float g_Sc[BHH*NCH*MMF*DHH];
__device__ float g_Sp[BHH*NCH*MMF*DHH];
__device__ float g_zc[BHH*NCH*MMF];
__device__ float g_zp[BHH*NCH*MMF];
__device__ float g_P [BHH*NCH*128*128];

// ---------------- helpers ----------------
__device__ __forceinline__ unsigned f_enc(float f){
    unsigned u = __float_as_uint(f);
    return (u & 0x80000000u) ? ~u : (u | 0x80000000u);
}
__device__ __forceinline__ float f_dec(unsigned u){
    return (u & 0x80000000u) ? __uint_as_float(u & 0x7fffffffu) : __uint_as_float(~u);
}
__device__ __forceinline__ unsigned f2tf(float x){
    unsigned r; asm("cvt.rna.tf32.f32 %0, %1;" : "=r"(r) : "f"(x)); return r;
}

#define MMA_TF32(c, a, b) asm volatile( \
  "mma.sync.aligned.m16n8k8.row.col.f32.tf32.tf32.f32 " \
  "{%0,%1,%2,%3}, {%4,%5,%6,%7}, {%8,%9}, {%0,%1,%2,%3};" \
  : "+f"(c[0]),"+f"(c[1]),"+f"(c[2]),"+f"(c[3]) \
  : "r"(a[0]),"r"(a[1]),"r"(a[2]),"r"(a[3]), "r"(b[0]),"r"(b[1]))

// ---------------- embedding + right-shift with SOS ----------------
__global__ void embed_kernel(const int* __restrict__ value, const int* __restrict__ depth,
                             const int* __restrict__ pos,   const float* __restrict__ sos,
                             const float* __restrict__ tok, const float* __restrict__ dep,
                             const float* __restrict__ spa)
{
    int i = blockIdx.x * 256 + threadIdx.x;
    if (i >= BSR*EE) return;
    int e = i & (EE-1);
    int r = i >> 9;            // row = b*S + s
    int b = r / SS, s = r - b*SS;
    float val;
    if (s == 0) {
        val = sos[e];
    } else {
        int p = b*SS + s - 1;
        val = tok[value[p]*EE + e] + dep[depth[p]*EE + e];
        #pragma unroll
        for (int a = 0; a < AAX; a++)
            val += spa[(size_t)a*65*EE + pos[p*AAX + a]*EE + e];
    }
    g_x[i] = val;
}

// ---------------- layernorm (row = 512) ----------------
__global__ __launch_bounds__(128) void ln_kernel(const float* __restrict__ in, float* __restrict__ out,
                                                 const float* __restrict__ w, const float* __restrict__ bia)
{
    int r = blockIdx.x, t = threadIdx.x;
    const float4 v = ((const float4*)(in + (size_t)r*EE))[t];
    float s  = v.x + v.y + v.z + v.w;
    float sq = v.x*v.x + v.y*v.y + v.z*v.z + v.w*v.w;
    #pragma unroll
    for (int o = 16; o; o >>= 1){ s += __shfl_xor_sync(~0u, s, o); sq += __shfl_xor_sync(~0u, sq, o); }
    __shared__ float sh[8];
    if ((t & 31) == 0){ sh[t>>5] = s; sh[4 + (t>>5)] = sq; }
    __syncthreads();
    s  = sh[0]+sh[1]+sh[2]+sh[3];
    sq = sh[4]+sh[5]+sh[6]+sh[7];
    float mu  = s * (1.f/EE);
    float var = sq * (1.f/EE) - mu*mu;
    float rs  = rsqrtf(var + 1e-5f);
    float4 wv = ((const float4*)w)[t], bv = ((const float4*)bia)[t];
    float4 o4;
    o4.x = (v.x-mu)*rs*wv.x + bv.x;
    o4.y = (v.y-mu)*rs*wv.y + bv.y;
    o4.z = (v.z-mu)*rs*wv.z + bv.z;
    o4.w = (v.w-mu)*rs*wv.w + bv.w;
    ((float4*)(out + (size_t)r*EE))[t] = o4;
}

// ---------------- tf32 tensor-core GEMM ----------------
// C[M,N] = A[M,K] @ B[K,N] + bias (+gelu) (+resid)
// 128x128 tile, BK=16 double-buffered, 8 warps of 64x32, mma.m16n8k8.tf32
#define BKK 16
#define LDA 132   // BM + 4 pad
#define LDB 132

__device__ __forceinline__ void gemm_body(
    const float* __restrict__ Am, const float* __restrict__ Bm,
    const float* __restrict__ bias, const float* __restrict__ resid,
    float* __restrict__ C, int N, int K, int act,
    unsigned* As, unsigned* Bs)
{
    const int tid = threadIdx.x;
    const int bm = blockIdx.y * 128, bn = blockIdx.x * 128;
    const int w = tid >> 5, lane = tid & 31;
    const int wm = (w & 1) * 64, wn = (w >> 1) * 32;
    const int lr = lane >> 2, lc = lane & 3;

    float acc[4][4][4];
    #pragma unroll
    for (int i = 0; i < 4; i++)
        #pragma unroll
        for (int j = 0; j < 4; j++)
            #pragma unroll
            for (int t = 0; t < 4; t++) acc[i][j][t] = 0.f;

    // gmem staging addressing: A tile 128x16 as 512 float4; B tile 16x128 same
    const int f0 = tid, f1 = tid + 256;
    const int ar0 = f0 >> 2, ak0 = (f0 & 3) << 2;
    const int ar1 = f1 >> 2, ak1 = (f1 & 3) << 2;
    const int br0 = f0 >> 5, bc0 = (f0 & 31) << 2;
    const int br1 = f1 >> 5, bc1 = (f1 & 31) << 2;

    float4 a4[2], b4[2];
    const int nk = K / BKK;

    // prologue: load k-block 0
    a4[0] = *(const float4*)&Am[(size_t)(bm + ar0)*K + ak0];
    a4[1] = *(const float4*)&Am[(size_t)(bm + ar1)*K + ak1];
    b4[0] = *(const float4*)&Bm[(size_t)br0*N + bn + bc0];
    b4[1] = *(const float4*)&Bm[(size_t)br1*N + bn + bc1];
    {
        unsigned* Ab = As; unsigned* Bb = Bs;
        Ab[(ak0+0)*LDA + ar0] = f2tf(a4[0].x); Ab[(ak0+1)*LDA + ar0] = f2tf(a4[0].y);
        Ab[(ak0+2)*LDA + ar0] = f2tf(a4[0].z); Ab[(ak0+3)*LDA + ar0] = f2tf(a4[0].w);
        Ab[(ak1+0)*LDA + ar1] = f2tf(a4[1].x); Ab[(ak1+1)*LDA + ar1] = f2tf(a4[1].y);
        Ab[(ak1+2)*LDA + ar1] = f2tf(a4[1].z); Ab[(ak1+3)*LDA + ar1] = f2tf(a4[1].w);
        Bb[br0*LDB + bc0+0] = f2tf(b4[0].x); Bb[br0*LDB + bc0+1] = f2tf(b4[0].y);
        Bb[br0*LDB + bc0+2] = f2tf(b4[0].z); Bb[br0*LDB + bc0+3] = f2tf(b4[0].w);
        Bb[br1*LDB + bc1+0] = f2tf(b4[1].x); Bb[br1*LDB + bc1+1] = f2tf(b4[1].y);
        Bb[br1*LDB + bc1+2] = f2tf(b4[1].z); Bb[br1*LDB + bc1+3] = f2tf(b4[1].w);
    }
    __syncthreads();

    for (int it = 0; it < nk; it++){
        const int cur = it & 1;
        if (it + 1 < nk){
            const int k0 = (it + 1) * BKK;
            a4[0] = *(const float4*)&Am[(size_t)(bm + ar0)*K + k0 + ak0];
            a4[1] = *(const float4*)&Am[(size_t)(bm + ar1)*K + k0 + ak1];
            b4[0] = *(const float4*)&Bm[(size_t)(k0 + br0)*N + bn + bc0];
            b4[1] = *(const float4*)&Bm[(size_t)(k0 + br1)*N + bn + bc1];
        }
        // compute on buffer cur
        {
            const unsigned* Ab = As + cur * (BKK * LDA);
            const unsigned* Bb = Bs + cur * (BKK * LDB);
            #pragma unroll
            for (int ks = 0; ks < BKK; ks += 8){
                unsigned af[4][4], bf[4][2];
                #pragma unroll
                for (int mt = 0; mt < 4; mt++){
                    const int base = (ks + lc)*LDA + wm + mt*16 + lr;
                    af[mt][0] = Ab[base];
                    af[mt][1] = Ab[base + 8];
                    af[mt][2] = Ab[base + 4*LDA];
                    af[mt][3] = Ab[base + 4*LDA + 8];
                }
                #pragma unroll
                for (int nt = 0; nt < 4; nt++){
                    const int base = (ks + lc)*LDB + wn + nt*8 + lr;
                    bf[nt][0] = Bb[base];
                    bf[nt][1] = Bb[base + 4*LDB];
                }
                #pragma unroll
                for (int mt = 0; mt < 4; mt++)
                    #pragma unroll
                    for (int nt = 0; nt < 4; nt++)
                        MMA_TF32(acc[mt][nt], af[mt], bf[nt]);
            }
        }
        if (it + 1 < nk){
            unsigned* Ab = As + (cur ^ 1) * (BKK * LDA);
            unsigned* Bb = Bs + (cur ^ 1) * (BKK * LDB);
            Ab[(ak0+0)*LDA + ar0] = f2tf(a4[0].x); Ab[(ak0+1)*LDA + ar0] = f2tf(a4[0].y);
            Ab[(ak0+2)*LDA + ar0] = f2tf(a4[0].z); Ab[(ak0+3)*LDA + ar0] = f2tf(a4[0].w);
            Ab[(ak1+0)*LDA + ar1] = f2tf(a4[1].x); Ab[(ak1+1)*LDA + ar1] = f2tf(a4[1].y);
            Ab[(ak1+2)*LDA + ar1] = f2tf(a4[1].z); Ab[(ak1+3)*LDA + ar1] = f2tf(a4[1].w);
            Bb[br0*LDB + bc0+0] = f2tf(b4[0].x); Bb[br0*LDB + bc0+1] = f2tf(b4[0].y);
            Bb[br0*LDB + bc0+2] = f2tf(b4[0].z); Bb[br0*LDB + bc0+3] = f2tf(b4[0].w);
            Bb[br1*LDB + bc1+0] = f2tf(b4[1].x); Bb[br1*LDB + bc1+1] = f2tf(b4[1].y);
            Bb[br1*LDB + bc1+2] = f2tf(b4[1].z); Bb[br1*LDB + bc1+3] = f2tf(b4[1].w);
        }
        __syncthreads();
    }

    // epilogue
    #pragma unroll
    for (int mt = 0; mt < 4; mt++){
        const int r0 = bm + wm + mt*16 + lr;
        #pragma unroll
        for (int nt = 0; nt < 4; nt++){
            const int c0 = bn + wn + nt*8 + 2*lc;
            const float bx = bias[c0], by = bias[c0+1];
            #pragma unroll
            for (int half = 0; half < 2; half++){
                const int r = r0 + half*8;
                float v0 = acc[mt][nt][half*2+0] + bx;
                float v1 = acc[mt][nt][half*2+1] + by;
                if (act){
                    v0 = 0.5f*v0*(1.f + erff(v0*0.70710678118654752f));
                    v1 = 0.5f*v1*(1.f + erff(v1*0.70710678118654752f));
                }
                if (resid){
                    v0 += resid[(size_t)r*N + c0];
                    v1 += resid[(size_t)r*N + c0+1];
                }
                *(float2*)&C[(size_t)r*N + c0] = make_float2(v0, v1);
            }
        }
    }
}

__global__ __launch_bounds__(256) void tgemm_kernel(
    const float* __restrict__ A, const float* __restrict__ Bm,
    const float* __restrict__ bias, const float* __restrict__ resid,
    float* __restrict__ C, int N, int K, int act)
{
    __shared__ unsigned As[2*BKK*LDA];
    __shared__ unsigned Bs[2*BKK*LDB];
    gemm_body(A, Bm, bias, resid, C, N, K, act, As, Bs);
}

__global__ __launch_bounds__(256) void qkv_kernel(
    const float* __restrict__ A,
    const float* __restrict__ Wq, const float* __restrict__ Wk, const float* __restrict__ Wv,
    const float* __restrict__ bq, const float* __restrict__ bk, const float* __restrict__ bv,
    float* __restrict__ oq, float* __restrict__ ok, float* __restrict__ ov)
{
    __shared__ unsigned As[2*BKK*LDA];
    __shared__ unsigned Bs[2*BKK*LDB];
    const int z = blockIdx.z;
    const float* Bm  = (z == 0) ? Wq : (z == 1) ? Wk : Wv;
    const float* bi  = (z == 0) ? bq : (z == 1) ? bk : bv;
    float*       Cm  = (z == 0) ? oq : (z == 1) ? ok : ov;
    gemm_body(A, Bm, bi, nullptr, Cm, EE, EE, 0, As, Bs);
}

// ---------------- FAVOR+ query features ----------------
__global__ __launch_bounds__(128) void qfeat_kernel(const float* __restrict__ proj)
{
    __shared__ float pr[MMF][DHH+1];
    __shared__ float xd[DHH];
    __shared__ float red[8];
    const int t = threadIdx.x;
    for (int i = t; i < MMF*DHH; i += 128) pr[i>>6][i&63] = proj[i];
    const int bh = blockIdx.y;
    const int b = bh / HH, h = bh % HH;
    const int s0 = blockIdx.x * 32;
    for (int rr = 0; rr < 32; rr++){
        int s = s0 + rr;
        float sq = 0.f;
        if (t < DHH){
            float vv = g_q[(size_t)(b*SS + s)*EE + h*DHH + t] * DNQ;
            xd[t] = vv; sq = vv*vv;
        }
        #pragma unroll
        for (int o = 16; o; o >>= 1) sq += __shfl_xor_sync(~0u, sq, o);
        if ((t & 31) == 0) red[t>>5] = sq;
        __syncthreads();
        float diag = 0.5f * (red[0] + red[1]);
        float dd = 0.f;
        #pragma unroll
        for (int d = 0; d < DHH; d++) dd += xd[d] * pr[t][d];
        float mx = dd;
        #pragma unroll
        for (int o = 16; o; o >>= 1) mx = fmaxf(mx, __shfl_xor_sync(~0u, mx, o));
        if ((t & 31) == 0) red[4 + (t>>5)] = mx;
        __syncthreads();
        mx = fmaxf(fmaxf(red[4], red[5]), fmaxf(red[6], red[7]));
        g_qp[((size_t)bh*SS + s)*MMF + t] = RATIO * (expf(dd - diag - mx) + KEPS);
    }
}

// ---------------- key features: pass 1 (raw dd, diag, global max) ----------------
__global__ void reset_kmax_kernel(){ g_kmax = 0u; }

__global__ __launch_bounds__(128) void kfeat1_kernel(const float* __restrict__ proj)
{
    __shared__ float pr[MMF][DHH+1];
    __shared__ float xd[DHH];
    __shared__ float red[8];
    const int t = threadIdx.x;
    for (int i = t; i < MMF*DHH; i += 128) pr[i>>6][i&63] = proj[i];
    const int bh = blockIdx.y;
    const int b = bh / HH, h = bh % HH;
    const int s0 = blockIdx.x * 32;
    float runmax = -3.4e38f;
    for (int rr = 0; rr < 32; rr++){
        int s = s0 + rr;
        float sq = 0.f;
        if (t < DHH){
            float vv = g_k[(size_t)(b*SS + s)*EE + h*DHH + t] * DNQ;
            xd[t] = vv; sq = vv*vv;
        }
        #pragma unroll
        for (int o = 16; o; o >>= 1) sq += __shfl_xor_sync(~0u, sq, o);
        if ((t & 31) == 0) red[t>>5] = sq;
        __syncthreads();
        float diag = 0.5f * (red[0] + red[1]);
        float dd = 0.f;
        #pragma unroll
        for (int d = 0; d < DHH; d++) dd += xd[d] * pr[t][d];
        g_kp[((size_t)bh*SS + s)*MMF + t] = dd;
        if (t == 0) g_kdiag[bh*SS + s] = diag;
        runmax = fmaxf(runmax, dd);
        __syncthreads();
    }
    #pragma unroll
    for (int o = 16; o; o >>= 1) runmax = fmaxf(runmax, __shfl_xor_sync(~0u, runmax, o));
    if ((t & 31) == 0) red[4 + (t>>5)] = runmax;
    __syncthreads();
    if (t == 0){
        float m = fmaxf(fmaxf(red[4], red[5]), fmaxf(red[6], red[7]));
        atomicMax(&g_kmax, f_enc(m));
    }
}

// ---------------- key features: pass 2 (exp) ----------------
__global__ __launch_bounds__(512) void kfeat2_kernel()
{
    int i = blockIdx.x * 512 + threadIdx.x;
    float gm = f_dec(g_kmax);
    g_kp[i] = RATIO * (expf(g_kp[i] - g_kdiag[i >> 7] - gm) + KEPS);
}

// ---------------- per-chunk KV state: Sc[m,d], zc[m] ----------------
__global__ __launch_bounds__(256) void chunk_kv_kernel()
{
    const int c = blockIdx.x, bh = blockIdx.y;
    const int b = bh / HH, h = bh % HH;
    __shared__ float Kt[16][128];
    __shared__ float Vt[16][64];
    const int tid = threadIdx.x;
    const int ty = tid >> 4, tx = tid & 15;
    float acc[8][4]; float zacc[8];
    #pragma unroll
    for (int i = 0; i < 8; i++){ zacc[i] = 0.f;
        #pragma unroll
        for (int j = 0; j < 4; j++) acc[i][j] = 0.f; }

    for (int t0 = 0; t0 < 128; t0 += 16){
        #pragma unroll
        for (int i = 0; i < 2; i++){
            int f = tid + i*256;
            *(float4*)&Kt[f>>5][(f&31)<<2] =
                *(const float4*)&g_kp[((size_t)bh*SS + c*128 + t0 + (f>>5))*MMF + ((f&31)<<2)];
        }
        *(float4*)&Vt[tid>>4][(tid&15)<<2] =
            *(const float4*)&g_v[((size_t)(b*SS + c*128 + t0 + (tid>>4)))*EE + h*DHH + ((tid&15)<<2)];
        __syncthreads();
        #pragma unroll
        for (int tt = 0; tt < 16; tt++){
            float a[8], bv[4];
            *(float4*)(a  ) = *(const float4*)&Kt[tt][ty*8];
            *(float4*)(a+4) = *(const float4*)&Kt[tt][ty*8+4];
            *(float4*)(bv ) = *(const float4*)&Vt[tt][tx*4];
            #pragma unroll
            for (int i = 0; i < 8; i++){
                #pragma unroll
                for (int j = 0; j < 4; j++) acc[i][j] += a[i]*bv[j];
                if (tx == 0) zacc[i] += a[i];
            }
        }
        __syncthreads();
    }
    size_t base = ((size_t)(bh*NCH + c))*MMF;
    #pragma unroll
    for (int i = 0; i < 8; i++){
        int m = ty*8 + i;
        #pragma unroll
        for (int j = 0; j < 4; j++)
            g_Sc[(base + m)*DHH + tx*4 + j] = acc[i][j];
        if (tx == 0) g_zc[base + m] = zacc[i];
    }
}

// ---------------- exclusive prefix over chunks ----------------
__global__ __launch_bounds__(512) void chunk_prefix_kernel()
{
    const int bh = blockIdx.x, t = threadIdx.x;
    float run[16];
    #pragma unroll
    for (int j = 0; j < 16; j++) run[j] = 0.f;
    float rz = 0.f;
    for (int c = 0; c < NCH; c++){
        size_t base = ((size_t)(bh*NCH + c))*MMF*DHH;
        #pragma unroll
        for (int j = 0; j < 16; j++){
            int idx = t + j*512;
            g_Sp[base + idx] = run[j];
            run[j] += g_Sc[base + idx];
        }
        if (t < MMF){
            int zb = (bh*NCH + c)*MMF + t;
            g_zp[zb] = rz;
            rz += g_zc[zb];
        }
    }
}

// ---------------- intra-chunk P = mask(Q K^T) ----------------
__global__ __launch_bounds__(256) void chunk_p_kernel()
{
    const int c = blockIdx.x, bh = blockIdx.y;
    __shared__ float Qs[16][128];
    __shared__ float Ks[16][128];
    const int tid = threadIdx.x;
    const int ty = tid >> 4, tx = tid & 15;
    float acc[8][8];
    #pragma unroll
    for (int i = 0; i < 8; i++)
        #pragma unroll
        for (int j = 0; j < 8; j++) acc[i][j] = 0.f;

    const size_t rowbase = (size_t)bh*SS + c*128;
    for (int m0 = 0; m0 < 128; m0 += 16){
        #pragma unroll
        for (int i = 0; i < 2; i++){
            int f = tid + i*256;
            int trow = f >> 2, mq = (f & 3) << 2;
            float4 qv = *(const float4*)&g_qp[(rowbase + trow)*MMF + m0 + mq];
            Qs[mq+0][trow] = qv.x; Qs[mq+1][trow] = qv.y; Qs[mq+2][trow] = qv.z; Qs[mq+3][trow] = qv.w;
            float4 kv = *(const float4*)&g_kp[(rowbase + trow)*MMF + m0 + mq];
            Ks[mq+0][trow] = kv.x; Ks[mq+1][trow] = kv.y; Ks[mq+2][trow] = kv.z; Ks[mq+3][trow] = kv.w;
        }
        __syncthreads();
        #pragma unroll
        for (int mm = 0; mm < 16; mm++){
            float a[8], b[8];
            *(float4*)(a  ) = *(const float4*)&Qs[mm][ty*8];
            *(float4*)(a+4) = *(const float4*)&Qs[mm][ty*8+4];
            *(float4*)(b  ) = *(const float4*)&Ks[mm][tx*8];
            *(float4*)(b+4) = *(const float4*)&Ks[mm][tx*8+4];
            #pragma unroll
            for (int i = 0; i < 8; i++)
                #pragma unroll
                for (int j = 0; j < 8; j++) acc[i][j] += a[i]*b[j];
        }
        __syncthreads();
    }
    size_t pbase = ((size_t)(bh*NCH + c))*128;
    #pragma unroll
    for (int i = 0; i < 8; i++){
        int r = ty*8 + i;
        #pragma unroll
        for (int j = 0; j < 8; j++){
            int cc = tx*8 + j;
            g_P[(pbase + r)*128 + cc] = (cc <= r) ? acc[i][j] : 0.f;
        }
    }
}

// ---------------- out = ([P|Q] @ [v;1 | Sp;zp]) with fused denominator ----------------
__global__ __launch_bounds__(256) void chunk_o_kernel()
{
    const int c = blockIdx.x, bh = blockIdx.y;
    const int b = bh / HH, h = bh % HH;
    __shared__ float Gs[16][128];
    __shared__ float Hs[16][64];
    __shared__ float h2s[16];
    __shared__ float densh[128];
    const int tid = threadIdx.x;
    const int ty = tid >> 4, tx = tid & 15;
    float acc[8][4]; float den[8];
    #pragma unroll
    for (int i = 0; i < 8; i++){ den[i] = 0.f;
        #pragma unroll
        for (int j = 0; j < 4; j++) acc[i][j] = 0.f; }

    const size_t pbase = ((size_t)(bh*NCH + c))*128;
    const size_t qbase = (size_t)bh*SS + c*128;
    const size_t sbase = ((size_t)(bh*NCH + c))*MMF;

    for (int j0 = 0; j0 < 256; j0 += 16){
        #pragma unroll
        for (int i = 0; i < 2; i++){
            int f = tid + i*256;
            int trow = f >> 2, jq = (f & 3) << 2;
            float4 gv;
            if (j0 < 128)
                gv = *(const float4*)&g_P[(pbase + trow)*128 + j0 + jq];
            else
                gv = *(const float4*)&g_qp[(qbase + trow)*MMF + (j0 - 128) + jq];
            Gs[jq+0][trow] = gv.x; Gs[jq+1][trow] = gv.y; Gs[jq+2][trow] = gv.z; Gs[jq+3][trow] = gv.w;
        }
        {
            int jrow = tid >> 4, d4 = (tid & 15) << 2;
            float4 hv;
            if (j0 < 128)
                hv = *(const float4*)&g_v[((size_t)(b*SS + c*128 + j0 + jrow))*EE + h*DHH + d4];
            else
                hv = *(const float4*)&g_Sp[(sbase + (j0 - 128 + jrow))*DHH + d4];
            *(float4*)&Hs[jrow][d4] = hv;
        }
        if (tid < 16) h2s[tid] = (j0 < 128) ? 1.f : g_zp[sbase + (j0 - 128) + tid];
        __syncthreads();
        #pragma unroll
        for (int jj = 0; jj < 16; jj++){
            float a[8], bv[4];
            *(float4*)(a  ) = *(const float4*)&Gs[jj][ty*8];
            *(float4*)(a+4) = *(const float4*)&Gs[jj][ty*8+4];
            *(float4*)(bv ) = *(const float4*)&Hs[jj][tx*4];
            #pragma unroll
            for (int i = 0; i < 8; i++){
                #pragma unroll
                for (int j = 0; j < 4; j++) acc[i][j] += a[i]*bv[j];
                if (tx == 0) den[i] += a[i]*h2s[jj];
            }
        }
        __syncthreads();
    }
    if (tx == 0)
        #pragma unroll
        for (int i = 0; i < 8; i++) densh[ty*8 + i] = den[i];
    __syncthreads();
    #pragma unroll
    for (int i = 0; i < 8; i++){
        int r = ty*8 + i;
        float dinv = 1.f / (densh[r] + DEPS);
        #pragma unroll
        for (int j = 0; j < 4; j++)
            g_o[((size_t)(b*SS + c*128 + r))*EE + h*DHH + tx*4 + j] = acc[i][j]*dinv;
    }
}

// ---------------- head projection ----------------
__global__ __launch_bounds__(64) void head_kernel(const float* __restrict__ hw, float* __restrict__ out)
{
    __shared__ float xs[EE];
    const int r = blockIdx.x, t = threadIdx.x;
    ((float4*)xs)[t]      = ((const float4*)(g_x + (size_t)r*EE))[t];
    ((float4*)xs)[t + 64] = ((const float4*)(g_x + (size_t)r*EE))[t + 64];
    __syncthreads();
    if (t < NVOC){
        float acc = 0.f;
        #pragma unroll 8
        for (int k = 0; k < EE; k++) acc += xs[k] * hw[k*NVOC + t];
        out[(size_t)r*NVOC + t] = acc;
    }
}

// ---------------- host launch ----------------
extern "C" void kernel_launch(void* const* d_in, const int* in_sizes, int n_in,
                              void* d_out, int out_size)
{
    (void)in_sizes; (void)n_in; (void)out_size;
    const int*   value = (const int*)  d_in[0];
    const int*   depth = (const int*)  d_in[1];
    const int*   pos   = (const int*)  d_in[2];
    const float* proj  = (const float*)d_in[3];
    const float* sos   = (const float*)d_in[4];
    const float* tok   = (const float*)d_in[5];
    const float* dep   = (const float*)d_in[6];
    const float* spa   = (const float*)d_in[7];
    const float* ln1w  = (const float*)d_in[8];
    const float* ln1b  = (const float*)d_in[9];
    const float* Wq    = (const float*)d_in[10];
    const float* bq    = (const float*)d_in[11];
    const float* Wk    = (const float*)d_in[12];
    const float* bk    = (const float*)d_in[13];
    const float* Wv    = (const float*)d_in[14];
    const float* bv    = (const float*)d_in[15];
    const float* Wo    = (const float*)d_in[16];
    const float* bo    = (const float*)d_in[17];
    const float* ln2w  = (const float*)d_in[18];
    const float* ln2b  = (const float*)d_in[19];
    const float* W1    = (const float*)d_in[20];
    const float* b1    = (const float*)d_in[21];
    const float* W2    = (const float*)d_in[22];
    const float* b2    = (const float*)d_in[23];
    const float* hw    = (const float*)d_in[24];

    float *px, *ph, *pq, *pk, *pv, *po, *pff;
    cudaGetSymbolAddress((void**)&px,  g_x);
    cudaGetSymbolAddress((void**)&ph,  g_h);
    cudaGetSymbolAddress((void**)&pq,  g_q);
    cudaGetSymbolAddress((void**)&pk,  g_k);
    cudaGetSymbolAddress((void**)&pv,  g_v);
    cudaGetSymbolAddress((void**)&po,  g_o);
    cudaGetSymbolAddress((void**)&pff, g_ff);

    embed_kernel<<<(BSR*EE + 255)/256, 256>>>(value, depth, pos, sos, tok, dep, spa);

    dim3 g512(4, 32);        // N=512 GEMMs
    dim3 g2048(16, 32);      // N=2048 GEMM
    dim3 gqkv(4, 32, 3);
    dim3 gfeat(SS/32, BHH);
    dim3 gchunk(NCH, BHH);

    for (int l = 0; l < LL; l++){
        const float* prj = proj + (size_t)l*MMF*DHH;
        ln_kernel<<<BSR, 128>>>(px, ph, ln1w + l*EE, ln1b + l*EE);
        qkv_kernel<<<gqkv, 256>>>(ph,
            Wq + (size_t)l*EE*EE, Wk + (size_t)l*EE*EE, Wv + (size_t)l*EE*EE,
            bq + l*EE, bk + l*EE, bv + l*EE,
            pq, pk, pv);

        qfeat_kernel<<<gfeat, 128>>>(prj);
        reset_kmax_kernel<<<1, 1>>>();
        kfeat1_kernel<<<gfeat, 128>>>(prj);
        kfeat2_kernel<<<(BHH*SS*MMF)/512, 512>>>();

        chunk_kv_kernel<<<gchunk, 256>>>();
        chunk_prefix_kernel<<<BHH, 512>>>();
        chunk_p_kernel<<<gchunk, 256>>>();
        chunk_o_kernel<<<gchunk, 256>>>();

        tgemm_kernel<<<g512, 256>>>(po, Wo + (size_t)l*EE*EE, bo + l*EE, px, px, EE, EE, 0);
        ln_kernel<<<BSR, 128>>>(px, ph, ln2w + l*EE, ln2b + l*EE);
        tgemm_kernel<<<g2048, 256>>>(ph, W1 + (size_t)l*EE*FFD, b1 + l*FFD, nullptr, pff, FFD, EE, 1);
        tgemm_kernel<<<g512, 256>>>(pff, W2 + (size_t)l*FFD*EE, b2 + l*EE, px, px, EE, FFD, 0);
    }

    head_kernel<<<BSR, 64>>>(hw, (float*)d_out);
}

// round 3
// speedup vs baseline: 2.9120x; 1.3601x over previous
#include <cuda_runtime.h>
#include <cuda_bf16.h>
#include <math.h>

// ---------------- problem constants ----------------
#define BB   2
#define SS   2048
#define EE   512
#define HH   8
#define LL   4
#define DHH  64
#define MMF  128
#define AAX  3
#define NVOC 17
#define BHH  (BB*HH)      // 16
#define BSR  (BB*SS)      // 4096
#define NCH  (SS/128)     // 16
#define FFD  (4*EE)       // 2048

#define DNQ   0.3535533905932738f
#define RATIO 0.08838834764831845f
#define KEPS  1e-4f
#define DEPS  1e-6f

// ---------------- scratch ----------------
__device__ float g_x [BSR*EE];
__device__ float g_h [BSR*EE];
__device__ float g_q [BSR*EE];
__device__ float g_k [BSR*EE];
__device__ float g_v [BSR*EE];
__device__ float g_o [BSR*EE];
__device__ float g_ff[BSR*FFD];
__device__ float g_qp[BHH*SS*MMF];
__device__ float g_kp[BHH*SS*MMF];
__device__ unsigned g_kmax;
__device__ float g_Sc[BHH*NCH*MMF*DHH];
__device__ float g_Sp[BHH*NCH*MMF*DHH];
__device__ float g_zc[BHH*NCH*MMF];
__device__ float g_zp[BHH*NCH*MMF];
__device__ float g_P [BHH*NCH*128*128];
__device__ float g_den[BHH*SS];

// ---------------- helpers ----------------
__device__ __forceinline__ unsigned f_enc(float f){
    unsigned u = __float_as_uint(f);
    return (u & 0x80000000u) ? ~u : (u | 0x80000000u);
}
__device__ __forceinline__ float f_dec(unsigned u){
    return (u & 0x80000000u) ? __uint_as_float(u & 0x7fffffffu) : __uint_as_float(~u);
}
__device__ __forceinline__ unsigned f2tf(float x){
    unsigned r; asm("cvt.rna.tf32.f32 %0, %1;" : "=r"(r) : "f"(x)); return r;
}

#define MMA_TF32(c, a, b) asm volatile( \
  "mma.sync.aligned.m16n8k8.row.col.f32.tf32.tf32.f32 " \
  "{%0,%1,%2,%3}, {%4,%5,%6,%7}, {%8,%9}, {%0,%1,%2,%3};" \
  : "+f"(c[0]),"+f"(c[1]),"+f"(c[2]),"+f"(c[3]) \
  : "r"(a[0]),"r"(a[1]),"r"(a[2]),"r"(a[3]), "r"(b[0]),"r"(b[1]))

// split x -> hi/lo tf32 pair
__device__ __forceinline__ void tfsplit(float x, unsigned& hi, unsigned& lo){
    hi = f2tf(x);
    lo = f2tf(x - __uint_as_float(hi));
}

// ---------------- embedding ----------------
__global__ void embed_kernel(const int* __restrict__ value, const int* __restrict__ depth,
                             const int* __restrict__ pos,   const float* __restrict__ sos,
                             const float* __restrict__ tok, const float* __restrict__ dep,
                             const float* __restrict__ spa)
{
    int i = blockIdx.x * 256 + threadIdx.x;
    if (i >= BSR*EE) return;
    int e = i & (EE-1);
    int r = i >> 9;
    int b = r / SS, s = r - b*SS;
    float val;
    if (s == 0) val = sos[e];
    else {
        int p = b*SS + s - 1;
        val = tok[value[p]*EE + e] + dep[depth[p]*EE + e];
        #pragma unroll
        for (int a = 0; a < AAX; a++)
            val += spa[(size_t)a*65*EE + pos[p*AAX + a]*EE + e];
    }
    g_x[i] = val;
}

// ---------------- layernorm ----------------
__global__ __launch_bounds__(128) void ln_kernel(const float* __restrict__ in, float* __restrict__ out,
                                                 const float* __restrict__ w, const float* __restrict__ bia)
{
    int r = blockIdx.x, t = threadIdx.x;
    const float4 v = ((const float4*)(in + (size_t)r*EE))[t];
    float s  = v.x + v.y + v.z + v.w;
    float sq = v.x*v.x + v.y*v.y + v.z*v.z + v.w*v.w;
    #pragma unroll
    for (int o = 16; o; o >>= 1){ s += __shfl_xor_sync(~0u, s, o); sq += __shfl_xor_sync(~0u, sq, o); }
    __shared__ float sh[8];
    if ((t & 31) == 0){ sh[t>>5] = s; sh[4 + (t>>5)] = sq; }
    __syncthreads();
    s  = sh[0]+sh[1]+sh[2]+sh[3];
    sq = sh[4]+sh[5]+sh[6]+sh[7];
    float mu  = s * (1.f/EE);
    float var = sq * (1.f/EE) - mu*mu;
    float rs  = rsqrtf(var + 1e-5f);
    float4 wv = ((const float4*)w)[t], bv = ((const float4*)bia)[t];
    float4 o4;
    o4.x = (v.x-mu)*rs*wv.x + bv.x;
    o4.y = (v.y-mu)*rs*wv.y + bv.y;
    o4.z = (v.z-mu)*rs*wv.z + bv.z;
    o4.w = (v.w-mu)*rs*wv.w + bv.w;
    ((float4*)(out + (size_t)r*EE))[t] = o4;
}

// ---------------- tf32 GEMM (weights) ----------------
#define BKK 16
#define LDA 136
#define LDB 136

__device__ __forceinline__ void gemm_body(
    const float* __restrict__ Am, const float* __restrict__ Bm,
    const float* __restrict__ bias, const float* __restrict__ resid,
    float* __restrict__ C, int N, int K, int act,
    unsigned* As, unsigned* Bs)
{
    const int tid = threadIdx.x;
    const int bm = blockIdx.y * 128, bn = blockIdx.x * 128;
    const int w = tid >> 5, lane = tid & 31;
    const int wm = (w & 1) * 64, wn = (w >> 1) * 32;
    const int lr = lane >> 2, lc = lane & 3;

    float acc[4][4][4];
    #pragma unroll
    for (int i = 0; i < 4; i++)
        #pragma unroll
        for (int j = 0; j < 4; j++)
            #pragma unroll
            for (int t = 0; t < 4; t++) acc[i][j][t] = 0.f;

    const int f0 = tid, f1 = tid + 256;
    const int ar0 = f0 >> 2, ak0 = (f0 & 3) << 2;
    const int ar1 = f1 >> 2, ak1 = (f1 & 3) << 2;
    const int br0 = f0 >> 5, bc0 = (f0 & 31) << 2;
    const int br1 = f1 >> 5, bc1 = (f1 & 31) << 2;

    float4 a4[2], b4[2];
    const int nk = K / BKK;

    a4[0] = *(const float4*)&Am[(size_t)(bm + ar0)*K + ak0];
    a4[1] = *(const float4*)&Am[(size_t)(bm + ar1)*K + ak1];
    b4[0] = *(const float4*)&Bm[(size_t)br0*N + bn + bc0];
    b4[1] = *(const float4*)&Bm[(size_t)br1*N + bn + bc1];
    {
        unsigned* Ab = As; unsigned* Bb = Bs;
        Ab[(ak0+0)*LDA + ar0] = f2tf(a4[0].x); Ab[(ak0+1)*LDA + ar0] = f2tf(a4[0].y);
        Ab[(ak0+2)*LDA + ar0] = f2tf(a4[0].z); Ab[(ak0+3)*LDA + ar0] = f2tf(a4[0].w);
        Ab[(ak1+0)*LDA + ar1] = f2tf(a4[1].x); Ab[(ak1+1)*LDA + ar1] = f2tf(a4[1].y);
        Ab[(ak1+2)*LDA + ar1] = f2tf(a4[1].z); Ab[(ak1+3)*LDA + ar1] = f2tf(a4[1].w);
        Bb[br0*LDB + bc0+0] = f2tf(b4[0].x); Bb[br0*LDB + bc0+1] = f2tf(b4[0].y);
        Bb[br0*LDB + bc0+2] = f2tf(b4[0].z); Bb[br0*LDB + bc0+3] = f2tf(b4[0].w);
        Bb[br1*LDB + bc1+0] = f2tf(b4[1].x); Bb[br1*LDB + bc1+1] = f2tf(b4[1].y);
        Bb[br1*LDB + bc1+2] = f2tf(b4[1].z); Bb[br1*LDB + bc1+3] = f2tf(b4[1].w);
    }
    __syncthreads();

    for (int it = 0; it < nk; it++){
        const int cur = it & 1;
        if (it + 1 < nk){
            const int k0 = (it + 1) * BKK;
            a4[0] = *(const float4*)&Am[(size_t)(bm + ar0)*K + k0 + ak0];
            a4[1] = *(const float4*)&Am[(size_t)(bm + ar1)*K + k0 + ak1];
            b4[0] = *(const float4*)&Bm[(size_t)(k0 + br0)*N + bn + bc0];
            b4[1] = *(const float4*)&Bm[(size_t)(k0 + br1)*N + bn + bc1];
        }
        {
            const unsigned* Ab = As + cur * (BKK * LDA);
            const unsigned* Bb = Bs + cur * (BKK * LDB);
            #pragma unroll
            for (int ks = 0; ks < BKK; ks += 8){
                unsigned af[4][4], bf[4][2];
                #pragma unroll
                for (int mt = 0; mt < 4; mt++){
                    const int base = (ks + lc)*LDA + wm + mt*16 + lr;
                    af[mt][0] = Ab[base];
                    af[mt][1] = Ab[base + 8];
                    af[mt][2] = Ab[base + 4*LDA];
                    af[mt][3] = Ab[base + 4*LDA + 8];
                }
                #pragma unroll
                for (int nt = 0; nt < 4; nt++){
                    const int base = (ks + lc)*LDB + wn + nt*8 + lr;
                    bf[nt][0] = Bb[base];
                    bf[nt][1] = Bb[base + 4*LDB];
                }
                #pragma unroll
                for (int mt = 0; mt < 4; mt++)
                    #pragma unroll
                    for (int nt = 0; nt < 4; nt++)
                        MMA_TF32(acc[mt][nt], af[mt], bf[nt]);
            }
        }
        if (it + 1 < nk){
            unsigned* Ab = As + (cur ^ 1) * (BKK * LDA);
            unsigned* Bb = Bs + (cur ^ 1) * (BKK * LDB);
            Ab[(ak0+0)*LDA + ar0] = f2tf(a4[0].x); Ab[(ak0+1)*LDA + ar0] = f2tf(a4[0].y);
            Ab[(ak0+2)*LDA + ar0] = f2tf(a4[0].z); Ab[(ak0+3)*LDA + ar0] = f2tf(a4[0].w);
            Ab[(ak1+0)*LDA + ar1] = f2tf(a4[1].x); Ab[(ak1+1)*LDA + ar1] = f2tf(a4[1].y);
            Ab[(ak1+2)*LDA + ar1] = f2tf(a4[1].z); Ab[(ak1+3)*LDA + ar1] = f2tf(a4[1].w);
            Bb[br0*LDB + bc0+0] = f2tf(b4[0].x); Bb[br0*LDB + bc0+1] = f2tf(b4[0].y);
            Bb[br0*LDB + bc0+2] = f2tf(b4[0].z); Bb[br0*LDB + bc0+3] = f2tf(b4[0].w);
            Bb[br1*LDB + bc1+0] = f2tf(b4[1].x); Bb[br1*LDB + bc1+1] = f2tf(b4[1].y);
            Bb[br1*LDB + bc1+2] = f2tf(b4[1].z); Bb[br1*LDB + bc1+3] = f2tf(b4[1].w);
        }
        __syncthreads();
    }

    #pragma unroll
    for (int mt = 0; mt < 4; mt++){
        const int r0 = bm + wm + mt*16 + lr;
        #pragma unroll
        for (int nt = 0; nt < 4; nt++){
            const int c0 = bn + wn + nt*8 + 2*lc;
            const float bx = bias[c0], by = bias[c0+1];
            #pragma unroll
            for (int half = 0; half < 2; half++){
                const int r = r0 + half*8;
                float v0 = acc[mt][nt][half*2+0] + bx;
                float v1 = acc[mt][nt][half*2+1] + by;
                if (act){
                    v0 = 0.5f*v0*(1.f + erff(v0*0.70710678118654752f));
                    v1 = 0.5f*v1*(1.f + erff(v1*0.70710678118654752f));
                }
                if (resid){
                    v0 += resid[(size_t)r*N + c0];
                    v1 += resid[(size_t)r*N + c0+1];
                }
                *(float2*)&C[(size_t)r*N + c0] = make_float2(v0, v1);
            }
        }
    }
}

__global__ __launch_bounds__(256) void tgemm_kernel(
    const float* __restrict__ A, const float* __restrict__ Bm,
    const float* __restrict__ bias, const float* __restrict__ resid,
    float* __restrict__ C, int N, int K, int act)
{
    __shared__ unsigned As[2*BKK*LDA];
    __shared__ unsigned Bs[2*BKK*LDB];
    gemm_body(A, Bm, bias, resid, C, N, K, act, As, Bs);
}

__global__ __launch_bounds__(256) void qkv_kernel(
    const float* __restrict__ A,
    const float* __restrict__ Wq, const float* __restrict__ Wk, const float* __restrict__ Wv,
    const float* __restrict__ bq, const float* __restrict__ bk, const float* __restrict__ bv,
    float* __restrict__ oq, float* __restrict__ ok, float* __restrict__ ov)
{
    __shared__ unsigned As[2*BKK*LDA];
    __shared__ unsigned Bs[2*BKK*LDB];
    const int z = blockIdx.z;
    const float* Bm  = (z == 0) ? Wq : (z == 1) ? Wk : Wv;
    const float* bi  = (z == 0) ? bq : (z == 1) ? bk : bv;
    float*       Cm  = (z == 0) ? oq : (z == 1) ? ok : ov;
    gemm_body(A, Bm, bi, nullptr, Cm, EE, EE, 0, As, Bs);
}

// ================= FAVOR features via 3xTF32 MMA =================
// block: (chunk c, bh, isq). dd[128 rows][128 feats] = (x*DNQ) @ proj^T, K=64
__global__ void reset_kmax_kernel(){ g_kmax = 0u; }

__global__ __launch_bounds__(256) void feat_kernel(const float* __restrict__ proj)
{
    __shared__ unsigned Ah[16*LDA], Al[16*LDA], Bh[16*LDB], Bl[16*LDB];
    __shared__ float diag[128];
    __shared__ unsigned rmax[128];
    __shared__ unsigned bmax;
    const int tid = threadIdx.x;
    const int c = blockIdx.x, bh = blockIdx.y;
    const int isq = (blockIdx.z == 0);
    const int b = bh / HH, h = bh % HH;
    const float* src = isq ? g_q : g_k;
    const int w = tid >> 5, lane = tid & 31;
    const int wm = (w & 1) * 64, wn = (w >> 1) * 32;
    const int lr = lane >> 2, lc = lane & 3;

    if (tid < 128) rmax[tid] = 0u;
    if (tid == 0) bmax = 0u;

    float acc[4][4][4];
    #pragma unroll
    for (int i = 0; i < 4; i++)
        #pragma unroll
        for (int j = 0; j < 4; j++)
            #pragma unroll
            for (int t = 0; t < 4; t++) acc[i][j][t] = 0.f;

    const int rrow = tid >> 1, kg = (tid & 1) * 8;
    float sq = 0.f;

    for (int kit = 0; kit < 4; kit++){
        const int k0 = kit * 16;
        // A: x rows (scaled)
        #pragma unroll
        for (int q4 = 0; q4 < 2; q4++){
            float4 a = *(const float4*)&src[((size_t)(b*SS + c*128 + rrow))*EE + h*DHH + k0 + kg + q4*4];
            float vals[4] = {a.x*DNQ, a.y*DNQ, a.z*DNQ, a.w*DNQ};
            #pragma unroll
            for (int i = 0; i < 4; i++){
                sq += vals[i]*vals[i];
                unsigned hi, lo; tfsplit(vals[i], hi, lo);
                Ah[(kg + q4*4 + i)*LDA + rrow] = hi;
                Al[(kg + q4*4 + i)*LDA + rrow] = lo;
            }
        }
        // B: proj rows
        #pragma unroll
        for (int q4 = 0; q4 < 2; q4++){
            float4 p = *(const float4*)&proj[rrow*DHH + k0 + kg + q4*4];
            float vals[4] = {p.x, p.y, p.z, p.w};
            #pragma unroll
            for (int i = 0; i < 4; i++){
                unsigned hi, lo; tfsplit(vals[i], hi, lo);
                Bh[(kg + q4*4 + i)*LDB + rrow] = hi;
                Bl[(kg + q4*4 + i)*LDB + rrow] = lo;
            }
        }
        __syncthreads();
        #pragma unroll
        for (int ks = 0; ks < 16; ks += 8){
            unsigned afh[4][4], afl[4][4], bfh[4][2], bfl[4][2];
            #pragma unroll
            for (int mt = 0; mt < 4; mt++){
                const int base = (ks + lc)*LDA + wm + mt*16 + lr;
                afh[mt][0] = Ah[base];        afl[mt][0] = Al[base];
                afh[mt][1] = Ah[base + 8];    afl[mt][1] = Al[base + 8];
                afh[mt][2] = Ah[base + 4*LDA];afl[mt][2] = Al[base + 4*LDA];
                afh[mt][3] = Ah[base + 4*LDA + 8]; afl[mt][3] = Al[base + 4*LDA + 8];
            }
            #pragma unroll
            for (int nt = 0; nt < 4; nt++){
                const int base = (ks + lc)*LDB + wn + nt*8 + lr;
                bfh[nt][0] = Bh[base];         bfl[nt][0] = Bl[base];
                bfh[nt][1] = Bh[base + 4*LDB]; bfl[nt][1] = Bl[base + 4*LDB];
            }
            #pragma unroll
            for (int mt = 0; mt < 4; mt++)
                #pragma unroll
                for (int nt = 0; nt < 4; nt++){
                    MMA_TF32(acc[mt][nt], afh[mt], bfh[nt]);
                    MMA_TF32(acc[mt][nt], afh[mt], bfl[nt]);
                    MMA_TF32(acc[mt][nt], afl[mt], bfh[nt]);
                }
        }
        __syncthreads();
    }
    // diag
    {
        float other = __shfl_xor_sync(~0u, sq, 1);
        if ((tid & 1) == 0) diag[rrow] = 0.5f * (sq + other);
    }
    // max reductions on raw dd
    if (isq){
        #pragma unroll
        for (int mt = 0; mt < 4; mt++)
            #pragma unroll
            for (int half = 0; half < 2; half++){
                const int r = wm + mt*16 + lr + half*8;
                float m = -3.4e38f;
                #pragma unroll
                for (int nt = 0; nt < 4; nt++){
                    m = fmaxf(m, acc[mt][nt][half*2+0]);
                    m = fmaxf(m, acc[mt][nt][half*2+1]);
                }
                atomicMax(&rmax[r], f_enc(m));
            }
    } else {
        float m = -3.4e38f;
        #pragma unroll
        for (int mt = 0; mt < 4; mt++)
            #pragma unroll
            for (int nt = 0; nt < 4; nt++)
                #pragma unroll
                for (int t = 0; t < 4; t++) m = fmaxf(m, acc[mt][nt][t]);
        #pragma unroll
        for (int o = 16; o; o >>= 1) m = fmaxf(m, __shfl_xor_sync(~0u, m, o));
        if (lane == 0) atomicMax(&bmax, f_enc(m));
    }
    __syncthreads();

    const size_t qbase = (size_t)bh*SS + c*128;
    if (isq){
        #pragma unroll
        for (int mt = 0; mt < 4; mt++)
            #pragma unroll
            for (int half = 0; half < 2; half++){
                const int r = wm + mt*16 + lr + half*8;
                const float dg = diag[r], mx = f_dec(rmax[r]);
                #pragma unroll
                for (int nt = 0; nt < 4; nt++){
                    const int c0 = wn + nt*8 + 2*lc;
                    float v0 = RATIO*(expf(acc[mt][nt][half*2+0] - dg - mx) + KEPS);
                    float v1 = RATIO*(expf(acc[mt][nt][half*2+1] - dg - mx) + KEPS);
                    *(float2*)&g_qp[(qbase + r)*MMF + c0] = make_float2(v0, v1);
                }
            }
    } else {
        if (tid == 0) atomicMax(&g_kmax, bmax);
        #pragma unroll
        for (int mt = 0; mt < 4; mt++)
            #pragma unroll
            for (int half = 0; half < 2; half++){
                const int r = wm + mt*16 + lr + half*8;
                const float dg = diag[r];
                #pragma unroll
                for (int nt = 0; nt < 4; nt++){
                    const int c0 = wn + nt*8 + 2*lc;
                    float v0 = acc[mt][nt][half*2+0] - dg;
                    float v1 = acc[mt][nt][half*2+1] - dg;
                    *(float2*)&g_kp[(qbase + r)*MMF + c0] = make_float2(v0, v1);
                }
            }
    }
}

// k features pass 2: exp with global max
__global__ __launch_bounds__(512) void kfeat2_kernel()
{
    int i = blockIdx.x * 512 + threadIdx.x;
    float gm = f_dec(g_kmax);
    g_kp[i] = RATIO * (expf(g_kp[i] - gm) + KEPS);
}

// per-chunk z: zc[m] = sum_t kp[t][m]
__global__ __launch_bounds__(128) void zc_kernel()
{
    const int c = blockIdx.x, bh = blockIdx.y, m = threadIdx.x;
    const size_t qbase = (size_t)bh*SS + c*128;
    float s = 0.f;
    for (int t = 0; t < 128; t++) s += g_kp[(qbase + t)*MMF + m];
    g_zc[(bh*NCH + c)*MMF + m] = s;
}

// ================= chunk Sc[m][d] = kp^T @ v via 3xTF32 =================
#define KVLDB 72
__global__ __launch_bounds__(256) void chunk_kv_kernel()
{
    __shared__ unsigned Ah[16*LDA], Al[16*LDA], Bh[16*KVLDB], Bl[16*KVLDB];
    const int c = blockIdx.x, bh = blockIdx.y;
    const int b = bh / HH, h = bh % HH;
    const int tid = threadIdx.x;
    const int w = tid >> 5, lane = tid & 31;
    const int wm = (w & 1) * 64, wn = (w >> 1) * 16;
    const int lr = lane >> 2, lc = lane & 3;
    const size_t qbase = (size_t)bh*SS + c*128;

    float acc[4][2][4];
    #pragma unroll
    for (int i = 0; i < 4; i++)
        #pragma unroll
        for (int j = 0; j < 2; j++)
            #pragma unroll
            for (int t = 0; t < 4; t++) acc[i][j][t] = 0.f;

    // A load: 16 t-rows x 128 m : thread t=tid>>4, m0=(tid&15)*8
    const int at = tid >> 4, am0 = (tid & 15) * 8;
    // B load: 16 t-rows x 64 d : thread t=tid>>4, d0=(tid&15)*4
    const int bt = tid >> 4, bd0 = (tid & 15) * 4;

    for (int kit = 0; kit < 8; kit++){
        const int t0 = kit * 16;
        #pragma unroll
        for (int q4 = 0; q4 < 2; q4++){
            float4 a = *(const float4*)&g_kp[(qbase + t0 + at)*MMF + am0 + q4*4];
            float vals[4] = {a.x, a.y, a.z, a.w};
            #pragma unroll
            for (int i = 0; i < 4; i++){
                unsigned hi, lo; tfsplit(vals[i], hi, lo);
                Ah[at*LDA + am0 + q4*4 + i] = hi;
                Al[at*LDA + am0 + q4*4 + i] = lo;
            }
        }
        {
            float4 vv = *(const float4*)&g_v[((size_t)(b*SS + c*128 + t0 + bt))*EE + h*DHH + bd0];
            float vals[4] = {vv.x, vv.y, vv.z, vv.w};
            #pragma unroll
            for (int i = 0; i < 4; i++){
                unsigned hi, lo; tfsplit(vals[i], hi, lo);
                Bh[bt*KVLDB + bd0 + i] = hi;
                Bl[bt*KVLDB + bd0 + i] = lo;
            }
        }
        __syncthreads();
        // note: A logical [m][t] stored As[t*LDA+m]; mma A-frag reads A[m][k=t]
        #pragma unroll
        for (int ks = 0; ks < 16; ks += 8){
            unsigned afh[4][4], afl[4][4], bfh[2][2], bfl[2][2];
            #pragma unroll
            for (int mt = 0; mt < 4; mt++){
                const int base = (ks + lc)*LDA + wm + mt*16 + lr;
                afh[mt][0] = Ah[base];         afl[mt][0] = Al[base];
                afh[mt][1] = Ah[base + 8];     afl[mt][1] = Al[base + 8];
                afh[mt][2] = Ah[base + 4*LDA]; afl[mt][2] = Al[base + 4*LDA];
                afh[mt][3] = Ah[base + 4*LDA + 8]; afl[mt][3] = Al[base + 4*LDA + 8];
            }
            #pragma unroll
            for (int nt = 0; nt < 2; nt++){
                const int base = (ks + lc)*KVLDB + wn + nt*8 + lr;
                bfh[nt][0] = Bh[base];           bfl[nt][0] = Bl[base];
                bfh[nt][1] = Bh[base + 4*KVLDB]; bfl[nt][1] = Bl[base + 4*KVLDB];
            }
            #pragma unroll
            for (int mt = 0; mt < 4; mt++)
                #pragma unroll
                for (int nt = 0; nt < 2; nt++){
                    MMA_TF32(acc[mt][nt], afh[mt], bfh[nt]);
                    MMA_TF32(acc[mt][nt], afh[mt], bfl[nt]);
                    MMA_TF32(acc[mt][nt], afl[mt], bfh[nt]);
                }
        }
        __syncthreads();
    }
    const size_t base = ((size_t)(bh*NCH + c))*MMF;
    #pragma unroll
    for (int mt = 0; mt < 4; mt++)
        #pragma unroll
        for (int half = 0; half < 2; half++){
            const int m = wm + mt*16 + lr + half*8;
            #pragma unroll
            for (int nt = 0; nt < 2; nt++){
                const int d0 = wn + nt*8 + 2*lc;
                *(float2*)&g_Sc[(base + m)*DHH + d0] =
                    make_float2(acc[mt][nt][half*2+0], acc[mt][nt][half*2+1]);
            }
        }
}

// ---------------- parallel exclusive prefix over chunks ----------------
__global__ __launch_bounds__(1024) void chunk_prefix_kernel()
{
    const int bh = blockIdx.y;
    const int idx = blockIdx.x * 1024 + threadIdx.x;   // 0..8191 = m*64+d
    float run = 0.f;
    #pragma unroll
    for (int c = 0; c < NCH; c++){
        size_t off = ((size_t)(bh*NCH + c))*MMF*DHH + idx;
        float v = g_Sc[off];
        g_Sp[off] = run;
        run += v;
    }
    if (blockIdx.x == 0 && threadIdx.x < MMF){
        const int m = threadIdx.x;
        float rz = 0.f;
        #pragma unroll
        for (int c = 0; c < NCH; c++){
            int zb = (bh*NCH + c)*MMF + m;
            g_zp[zb] = rz;
            rz += g_zc[zb];
        }
    }
}

// ================= P = mask(qp @ kp^T) via 3xTF32 =================
__global__ __launch_bounds__(256) void chunk_p_kernel()
{
    __shared__ unsigned Ah[16*LDA], Al[16*LDA], Bh[16*LDB], Bl[16*LDB];
    const int c = blockIdx.x, bh = blockIdx.y;
    const int tid = threadIdx.x;
    const int w = tid >> 5, lane = tid & 31;
    const int wm = (w & 1) * 64, wn = (w >> 1) * 32;
    const int lr = lane >> 2, lc = lane & 3;
    const size_t qbase = (size_t)bh*SS + c*128;

    float acc[4][4][4];
    #pragma unroll
    for (int i = 0; i < 4; i++)
        #pragma unroll
        for (int j = 0; j < 4; j++)
            #pragma unroll
            for (int t = 0; t < 4; t++) acc[i][j][t] = 0.f;

    const int rrow = tid >> 1, kg = (tid & 1) * 8;

    for (int kit = 0; kit < 8; kit++){
        const int m0 = kit * 16;
        #pragma unroll
        for (int q4 = 0; q4 < 2; q4++){
            float4 a = *(const float4*)&g_qp[(qbase + rrow)*MMF + m0 + kg + q4*4];
            float va[4] = {a.x, a.y, a.z, a.w};
            float4 bk = *(const float4*)&g_kp[(qbase + rrow)*MMF + m0 + kg + q4*4];
            float vb[4] = {bk.x, bk.y, bk.z, bk.w};
            #pragma unroll
            for (int i = 0; i < 4; i++){
                unsigned hi, lo;
                tfsplit(va[i], hi, lo);
                Ah[(kg + q4*4 + i)*LDA + rrow] = hi;
                Al[(kg + q4*4 + i)*LDA + rrow] = lo;
                tfsplit(vb[i], hi, lo);
                Bh[(kg + q4*4 + i)*LDB + rrow] = hi;
                Bl[(kg + q4*4 + i)*LDB + rrow] = lo;
            }
        }
        __syncthreads();
        #pragma unroll
        for (int ks = 0; ks < 16; ks += 8){
            unsigned afh[4][4], afl[4][4], bfh[4][2], bfl[4][2];
            #pragma unroll
            for (int mt = 0; mt < 4; mt++){
                const int base = (ks + lc)*LDA + wm + mt*16 + lr;
                afh[mt][0] = Ah[base];         afl[mt][0] = Al[base];
                afh[mt][1] = Ah[base + 8];     afl[mt][1] = Al[base + 8];
                afh[mt][2] = Ah[base + 4*LDA]; afl[mt][2] = Al[base + 4*LDA];
                afh[mt][3] = Ah[base + 4*LDA + 8]; afl[mt][3] = Al[base + 4*LDA + 8];
            }
            #pragma unroll
            for (int nt = 0; nt < 4; nt++){
                const int base = (ks + lc)*LDB + wn + nt*8 + lr;
                bfh[nt][0] = Bh[base];         bfl[nt][0] = Bl[base];
                bfh[nt][1] = Bh[base + 4*LDB]; bfl[nt][1] = Bl[base + 4*LDB];
            }
            #pragma unroll
            for (int mt = 0; mt < 4; mt++)
                #pragma unroll
                for (int nt = 0; nt < 4; nt++){
                    MMA_TF32(acc[mt][nt], afh[mt], bfh[nt]);
                    MMA_TF32(acc[mt][nt], afh[mt], bfl[nt]);
                    MMA_TF32(acc[mt][nt], afl[mt], bfh[nt]);
                }
        }
        __syncthreads();
    }
    const size_t pbase = ((size_t)(bh*NCH + c))*128;
    #pragma unroll
    for (int mt = 0; mt < 4; mt++)
        #pragma unroll
        for (int half = 0; half < 2; half++){
            const int r = wm + mt*16 + lr + half*8;
            #pragma unroll
            for (int nt = 0; nt < 4; nt++){
                const int c0 = wn + nt*8 + 2*lc;
                float v0 = (c0   <= r) ? acc[mt][nt][half*2+0] : 0.f;
                float v1 = (c0+1 <= r) ? acc[mt][nt][half*2+1] : 0.f;
                *(float2*)&g_P[(pbase + r)*128 + c0] = make_float2(v0, v1);
            }
        }
}

// ---------------- denominator: den[r] = rowsum(P[r]) + qp[r].zp ----------------
__global__ __launch_bounds__(128) void den_kernel()
{
    __shared__ float zps[MMF];
    const int c = blockIdx.x, bh = blockIdx.y;
    const int tid = threadIdx.x, w = tid >> 5, lane = tid & 31;
    const size_t pbase = ((size_t)(bh*NCH + c))*128;
    const size_t qbase = (size_t)bh*SS + c*128;
    const size_t sbase = ((size_t)(bh*NCH + c))*MMF;
    if (tid < MMF) zps[tid] = g_zp[sbase + tid];
    __syncthreads();
    for (int rr = 0; rr < 32; rr++){
        const int r = rr*4 + w;
        float4 p = *(const float4*)&g_P[(pbase + r)*128 + lane*4];
        float4 q = *(const float4*)&g_qp[(qbase + r)*MMF + lane*4];
        float4 z = *(const float4*)&zps[lane*4];
        float s = p.x + p.y + p.z + p.w + q.x*z.x + q.y*z.y + q.z*z.z + q.w*z.w;
        #pragma unroll
        for (int o = 16; o; o >>= 1) s += __shfl_xor_sync(~0u, s, o);
        if (lane == 0) g_den[qbase + r] = s;
    }
}

// ================= out = ([P|qp] @ [v;Sp]) / den via 3xTF32 =================
__global__ __launch_bounds__(256) void chunk_o_kernel()
{
    __shared__ unsigned Ah[16*LDA], Al[16*LDA], Bh[16*KVLDB], Bl[16*KVLDB];
    const int c = blockIdx.x, bh = blockIdx.y;
    const int b = bh / HH, h = bh % HH;
    const int tid = threadIdx.x;
    const int w = tid >> 5, lane = tid & 31;
    const int wm = (w & 1) * 64, wn = (w >> 1) * 16;
    const int lr = lane >> 2, lc = lane & 3;
    const size_t pbase = ((size_t)(bh*NCH + c))*128;
    const size_t qbase = (size_t)bh*SS + c*128;
    const size_t sbase = ((size_t)(bh*NCH + c))*MMF;

    float acc[4][2][4];
    #pragma unroll
    for (int i = 0; i < 4; i++)
        #pragma unroll
        for (int j = 0; j < 2; j++)
            #pragma unroll
            for (int t = 0; t < 4; t++) acc[i][j][t] = 0.f;

    const int rrow = tid >> 1, kg = (tid & 1) * 8;
    const int bt = tid >> 4, bd0 = (tid & 15) * 4;

    for (int kit = 0; kit < 16; kit++){
        const int j0 = kit * 16;
        #pragma unroll
        for (int q4 = 0; q4 < 2; q4++){
            float4 a;
            if (j0 < 128) a = *(const float4*)&g_P[(pbase + rrow)*128 + j0 + kg + q4*4];
            else          a = *(const float4*)&g_qp[(qbase + rrow)*MMF + (j0 - 128) + kg + q4*4];
            float vals[4] = {a.x, a.y, a.z, a.w};
            #pragma unroll
            for (int i = 0; i < 4; i++){
                unsigned hi, lo; tfsplit(vals[i], hi, lo);
                Ah[(kg + q4*4 + i)*LDA + rrow] = hi;
                Al[(kg + q4*4 + i)*LDA + rrow] = lo;
            }
        }
        {
            float4 hv;
            if (j0 < 128) hv = *(const float4*)&g_v[((size_t)(b*SS + c*128 + j0 + bt))*EE + h*DHH + bd0];
            else          hv = *(const float4*)&g_Sp[(sbase + (j0 - 128) + bt)*DHH + bd0];
            float vals[4] = {hv.x, hv.y, hv.z, hv.w};
            #pragma unroll
            for (int i = 0; i < 4; i++){
                unsigned hi, lo; tfsplit(vals[i], hi, lo);
                Bh[bt*KVLDB + bd0 + i] = hi;
                Bl[bt*KVLDB + bd0 + i] = lo;
            }
        }
        __syncthreads();
        #pragma unroll
        for (int ks = 0; ks < 16; ks += 8){
            unsigned afh[4][4], afl[4][4], bfh[2][2], bfl[2][2];
            #pragma unroll
            for (int mt = 0; mt < 4; mt++){
                const int base = (ks + lc)*LDA + wm + mt*16 + lr;
                afh[mt][0] = Ah[base];         afl[mt][0] = Al[base];
                afh[mt][1] = Ah[base + 8];     afl[mt][1] = Al[base + 8];
                afh[mt][2] = Ah[base + 4*LDA]; afl[mt][2] = Al[base + 4*LDA];
                afh[mt][3] = Ah[base + 4*LDA + 8]; afl[mt][3] = Al[base + 4*LDA + 8];
            }
            #pragma unroll
            for (int nt = 0; nt < 2; nt++){
                const int base = (ks + lc)*KVLDB + wn + nt*8 + lr;
                bfh[nt][0] = Bh[base];           bfl[nt][0] = Bl[base];
                bfh[nt][1] = Bh[base + 4*KVLDB]; bfl[nt][1] = Bl[base + 4*KVLDB];
            }
            #pragma unroll
            for (int mt = 0; mt < 4; mt++)
                #pragma unroll
                for (int nt = 0; nt < 2; nt++){
                    MMA_TF32(acc[mt][nt], afh[mt], bfh[nt]);
                    MMA_TF32(acc[mt][nt], afh[mt], bfl[nt]);
                    MMA_TF32(acc[mt][nt], afl[mt], bfh[nt]);
                }
        }
        __syncthreads();
    }
    #pragma unroll
    for (int mt = 0; mt < 4; mt++)
        #pragma unroll
        for (int half = 0; half < 2; half++){
            const int r = wm + mt*16 + lr + half*8;
            const float dinv = 1.f / (g_den[qbase + r] + DEPS);
            #pragma unroll
            for (int nt = 0; nt < 2; nt++){
                const int d0 = wn + nt*8 + 2*lc;
                *(float2*)&g_o[((size_t)(b*SS + c*128 + r))*EE + h*DHH + d0] =
                    make_float2(acc[mt][nt][half*2+0]*dinv, acc[mt][nt][half*2+1]*dinv);
            }
        }
}

// ---------------- head projection ----------------
__global__ __launch_bounds__(64) void head_kernel(const float* __restrict__ hw, float* __restrict__ out)
{
    __shared__ float xs[EE];
    const int r = blockIdx.x, t = threadIdx.x;
    ((float4*)xs)[t]      = ((const float4*)(g_x + (size_t)r*EE))[t];
    ((float4*)xs)[t + 64] = ((const float4*)(g_x + (size_t)r*EE))[t + 64];
    __syncthreads();
    if (t < NVOC){
        float acc = 0.f;
        #pragma unroll 8
        for (int k = 0; k < EE; k++) acc += xs[k] * hw[k*NVOC + t];
        out[(size_t)r*NVOC + t] = acc;
    }
}

// ---------------- host launch ----------------
extern "C" void kernel_launch(void* const* d_in, const int* in_sizes, int n_in,
                              void* d_out, int out_size)
{
    (void)in_sizes; (void)n_in; (void)out_size;
    const int*   value = (const int*)  d_in[0];
    const int*   depth = (const int*)  d_in[1];
    const int*   pos   = (const int*)  d_in[2];
    const float* proj  = (const float*)d_in[3];
    const float* sos   = (const float*)d_in[4];
    const float* tok   = (const float*)d_in[5];
    const float* dep   = (const float*)d_in[6];
    const float* spa   = (const float*)d_in[7];
    const float* ln1w  = (const float*)d_in[8];
    const float* ln1b  = (const float*)d_in[9];
    const float* Wq    = (const float*)d_in[10];
    const float* bq    = (const float*)d_in[11];
    const float* Wk    = (const float*)d_in[12];
    const float* bk    = (const float*)d_in[13];
    const float* Wv    = (const float*)d_in[14];
    const float* bv    = (const float*)d_in[15];
    const float* Wo    = (const float*)d_in[16];
    const float* bo    = (const float*)d_in[17];
    const float* ln2w  = (const float*)d_in[18];
    const float* ln2b  = (const float*)d_in[19];
    const float* W1    = (const float*)d_in[20];
    const float* b1    = (const float*)d_in[21];
    const float* W2    = (const float*)d_in[22];
    const float* b2    = (const float*)d_in[23];
    const float* hw    = (const float*)d_in[24];

    float *px, *ph, *pq, *pk, *pv, *po, *pff;
    cudaGetSymbolAddress((void**)&px,  g_x);
    cudaGetSymbolAddress((void**)&ph,  g_h);
    cudaGetSymbolAddress((void**)&pq,  g_q);
    cudaGetSymbolAddress((void**)&pk,  g_k);
    cudaGetSymbolAddress((void**)&pv,  g_v);
    cudaGetSymbolAddress((void**)&po,  g_o);
    cudaGetSymbolAddress((void**)&pff, g_ff);

    embed_kernel<<<(BSR*EE + 255)/256, 256>>>(value, depth, pos, sos, tok, dep, spa);

    dim3 g512(4, 32);
    dim3 g2048(16, 32);
    dim3 gqkv(4, 32, 3);
    dim3 gfeat(NCH, BHH, 2);
    dim3 gchunk(NCH, BHH);
    dim3 gprefix(8, BHH);

    for (int l = 0; l < LL; l++){
        const float* prj = proj + (size_t)l*MMF*DHH;
        ln_kernel<<<BSR, 128>>>(px, ph, ln1w + l*EE, ln1b + l*EE);
        qkv_kernel<<<gqkv, 256>>>(ph,
            Wq + (size_t)l*EE*EE, Wk + (size_t)l*EE*EE, Wv + (size_t)l*EE*EE,
            bq + l*EE, bk + l*EE, bv + l*EE,
            pq, pk, pv);

        reset_kmax_kernel<<<1, 1>>>();
        feat_kernel<<<gfeat, 256>>>(prj);
        kfeat2_kernel<<<(BHH*SS*MMF)/512, 512>>>();

        zc_kernel<<<gchunk, 128>>>();
        chunk_kv_kernel<<<gchunk, 256>>>();
        chunk_prefix_kernel<<<gprefix, 1024>>>();
        chunk_p_kernel<<<gchunk, 256>>>();
        den_kernel<<<gchunk, 128>>>();
        chunk_o_kernel<<<gchunk, 256>>>();

        tgemm_kernel<<<g512, 256>>>(po, Wo + (size_t)l*EE*EE, bo + l*EE, px, px, EE, EE, 0);
        ln_kernel<<<BSR, 128>>>(px, ph, ln2w + l*EE, ln2b + l*EE);
        tgemm_kernel<<<g2048, 256>>>(ph, W1 + (size_t)l*EE*FFD, b1 + l*FFD, nullptr, pff, FFD, EE, 1);
        tgemm_kernel<<<g512, 256>>>(pff, W2 + (size_t)l*FFD*EE, b2 + l*EE, px, px, EE, FFD, 0);
    }

    head_kernel<<<BSR, 64>>>(hw, (float*)d_out);
}

// round 4
// speedup vs baseline: 2.9773x; 1.0224x over previous
#include <cuda_runtime.h>
#include <cuda_bf16.h>
#include <math.h>

// ---------------- problem constants ----------------
#define BB   2
#define SS   2048
#define EE   512
#define HH   8
#define LL   4
#define DHH  64
#define MMF  128
#define AAX  3
#define NVOC 17
#define BHH  (BB*HH)      // 16
#define BSR  (BB*SS)      // 4096
#define NCH  (SS/128)     // 16
#define FFD  (4*EE)       // 2048

#define DNQ   0.3535533905932738f
#define RATIO 0.08838834764831845f
#define KEPS  1e-4f
#define DEPS  1e-6f

// ---------------- scratch ----------------
__device__ float g_x [BSR*EE];
__device__ float g_h [BSR*EE];
__device__ float g_q [BSR*EE];
__device__ float g_k [BSR*EE];
__device__ float g_v [BSR*EE];
__device__ float g_o [BSR*EE];
__device__ float g_ff[BSR*FFD];
__device__ float g_qp[BHH*SS*MMF];
__device__ float g_kp[BHH*SS*MMF];
__device__ unsigned g_kmaxv[LL];
__device__ float g_Sc[BHH*NCH*MMF*DHH];
__device__ float g_Sp[BHH*NCH*MMF*DHH];
__device__ float g_zc[BHH*NCH*MMF];
__device__ float g_zp[BHH*NCH*MMF];
__device__ float g_P [BHH*NCH*128*128];

// ---------------- helpers ----------------
__device__ __forceinline__ unsigned f_enc(float f){
    unsigned u = __float_as_uint(f);
    return (u & 0x80000000u) ? ~u : (u | 0x80000000u);
}
__device__ __forceinline__ float f_dec(unsigned u){
    return (u & 0x80000000u) ? __uint_as_float(u & 0x7fffffffu) : __uint_as_float(~u);
}
__device__ __forceinline__ unsigned f2tf(float x){
    unsigned r; asm("cvt.rna.tf32.f32 %0, %1;" : "=r"(r) : "f"(x)); return r;
}

#define MMA_TF32(c, a, b) asm volatile( \
  "mma.sync.aligned.m16n8k8.row.col.f32.tf32.tf32.f32 " \
  "{%0,%1,%2,%3}, {%4,%5,%6,%7}, {%8,%9}, {%0,%1,%2,%3};" \
  : "+f"(c[0]),"+f"(c[1]),"+f"(c[2]),"+f"(c[3]) \
  : "r"(a[0]),"r"(a[1]),"r"(a[2]),"r"(a[3]), "r"(b[0]),"r"(b[1]))

__device__ __forceinline__ void tfsplit(float x, unsigned& hi, unsigned& lo){
    hi = f2tf(x);
    lo = f2tf(x - __uint_as_float(hi));
}

// ---------------- embedding (+ per-layer kmax reset) ----------------
__global__ void embed_kernel(const int* __restrict__ value, const int* __restrict__ depth,
                             const int* __restrict__ pos,   const float* __restrict__ sos,
                             const float* __restrict__ tok, const float* __restrict__ dep,
                             const float* __restrict__ spa)
{
    if (blockIdx.x == 0 && threadIdx.x < LL) g_kmaxv[threadIdx.x] = 0u;
    int i = blockIdx.x * 256 + threadIdx.x;
    if (i >= BSR*EE) return;
    int e = i & (EE-1);
    int r = i >> 9;
    int b = r / SS, s = r - b*SS;
    float val;
    if (s == 0) val = sos[e];
    else {
        int p = b*SS + s - 1;
        val = tok[value[p]*EE + e] + dep[depth[p]*EE + e];
        #pragma unroll
        for (int a = 0; a < AAX; a++)
            val += spa[(size_t)a*65*EE + pos[p*AAX + a]*EE + e];
    }
    g_x[i] = val;
}

// ---------------- layernorm ----------------
__global__ __launch_bounds__(128) void ln_kernel(const float* __restrict__ in, float* __restrict__ out,
                                                 const float* __restrict__ w, const float* __restrict__ bia)
{
    int r = blockIdx.x, t = threadIdx.x;
    const float4 v = ((const float4*)(in + (size_t)r*EE))[t];
    float s  = v.x + v.y + v.z + v.w;
    float sq = v.x*v.x + v.y*v.y + v.z*v.z + v.w*v.w;
    #pragma unroll
    for (int o = 16; o; o >>= 1){ s += __shfl_xor_sync(~0u, s, o); sq += __shfl_xor_sync(~0u, sq, o); }
    __shared__ float sh[8];
    if ((t & 31) == 0){ sh[t>>5] = s; sh[4 + (t>>5)] = sq; }
    __syncthreads();
    s  = sh[0]+sh[1]+sh[2]+sh[3];
    sq = sh[4]+sh[5]+sh[6]+sh[7];
    float mu  = s * (1.f/EE);
    float var = sq * (1.f/EE) - mu*mu;
    float rs  = rsqrtf(var + 1e-5f);
    float4 wv = ((const float4*)w)[t], bv = ((const float4*)bia)[t];
    float4 o4;
    o4.x = (v.x-mu)*rs*wv.x + bv.x;
    o4.y = (v.y-mu)*rs*wv.y + bv.y;
    o4.z = (v.z-mu)*rs*wv.z + bv.z;
    o4.w = (v.w-mu)*rs*wv.w + bv.w;
    ((float4*)(out + (size_t)r*EE))[t] = o4;
}

// ---------------- tf32 GEMM (weights) ----------------
#define BKK 16
#define LDA 136
#define LDB 136

__device__ __forceinline__ void gemm_body(
    const float* __restrict__ Am, const float* __restrict__ Bm,
    const float* __restrict__ bias, const float* __restrict__ resid,
    float* __restrict__ C, int N, int K, int act,
    unsigned* As, unsigned* Bs)
{
    const int tid = threadIdx.x;
    const int bm = blockIdx.y * 128, bn = blockIdx.x * 128;
    const int w = tid >> 5, lane = tid & 31;
    const int wm = (w & 1) * 64, wn = (w >> 1) * 32;
    const int lr = lane >> 2, lc = lane & 3;

    float acc[4][4][4];
    #pragma unroll
    for (int i = 0; i < 4; i++)
        #pragma unroll
        for (int j = 0; j < 4; j++)
            #pragma unroll
            for (int t = 0; t < 4; t++) acc[i][j][t] = 0.f;

    const int f0 = tid, f1 = tid + 256;
    const int ar0 = f0 >> 2, ak0 = (f0 & 3) << 2;
    const int ar1 = f1 >> 2, ak1 = (f1 & 3) << 2;
    const int br0 = f0 >> 5, bc0 = (f0 & 31) << 2;
    const int br1 = f1 >> 5, bc1 = (f1 & 31) << 2;

    float4 a4[2], b4[2];
    const int nk = K / BKK;

    a4[0] = *(const float4*)&Am[(size_t)(bm + ar0)*K + ak0];
    a4[1] = *(const float4*)&Am[(size_t)(bm + ar1)*K + ak1];
    b4[0] = *(const float4*)&Bm[(size_t)br0*N + bn + bc0];
    b4[1] = *(const float4*)&Bm[(size_t)br1*N + bn + bc1];
    {
        unsigned* Ab = As; unsigned* Bb = Bs;
        Ab[(ak0+0)*LDA + ar0] = f2tf(a4[0].x); Ab[(ak0+1)*LDA + ar0] = f2tf(a4[0].y);
        Ab[(ak0+2)*LDA + ar0] = f2tf(a4[0].z); Ab[(ak0+3)*LDA + ar0] = f2tf(a4[0].w);
        Ab[(ak1+0)*LDA + ar1] = f2tf(a4[1].x); Ab[(ak1+1)*LDA + ar1] = f2tf(a4[1].y);
        Ab[(ak1+2)*LDA + ar1] = f2tf(a4[1].z); Ab[(ak1+3)*LDA + ar1] = f2tf(a4[1].w);
        Bb[br0*LDB + bc0+0] = f2tf(b4[0].x); Bb[br0*LDB + bc0+1] = f2tf(b4[0].y);
        Bb[br0*LDB + bc0+2] = f2tf(b4[0].z); Bb[br0*LDB + bc0+3] = f2tf(b4[0].w);
        Bb[br1*LDB + bc1+0] = f2tf(b4[1].x); Bb[br1*LDB + bc1+1] = f2tf(b4[1].y);
        Bb[br1*LDB + bc1+2] = f2tf(b4[1].z); Bb[br1*LDB + bc1+3] = f2tf(b4[1].w);
    }
    __syncthreads();

    for (int it = 0; it < nk; it++){
        const int cur = it & 1;
        if (it + 1 < nk){
            const int k0 = (it + 1) * BKK;
            a4[0] = *(const float4*)&Am[(size_t)(bm + ar0)*K + k0 + ak0];
            a4[1] = *(const float4*)&Am[(size_t)(bm + ar1)*K + k0 + ak1];
            b4[0] = *(const float4*)&Bm[(size_t)(k0 + br0)*N + bn + bc0];
            b4[1] = *(const float4*)&Bm[(size_t)(k0 + br1)*N + bn + bc1];
        }
        {
            const unsigned* Ab = As + cur * (BKK * LDA);
            const unsigned* Bb = Bs + cur * (BKK * LDB);
            #pragma unroll
            for (int ks = 0; ks < BKK; ks += 8){
                unsigned af[4][4], bf[4][2];
                #pragma unroll
                for (int mt = 0; mt < 4; mt++){
                    const int base = (ks + lc)*LDA + wm + mt*16 + lr;
                    af[mt][0] = Ab[base];
                    af[mt][1] = Ab[base + 8];
                    af[mt][2] = Ab[base + 4*LDA];
                    af[mt][3] = Ab[base + 4*LDA + 8];
                }
                #pragma unroll
                for (int nt = 0; nt < 4; nt++){
                    const int base = (ks + lc)*LDB + wn + nt*8 + lr;
                    bf[nt][0] = Bb[base];
                    bf[nt][1] = Bb[base + 4*LDB];
                }
                #pragma unroll
                for (int mt = 0; mt < 4; mt++)
                    #pragma unroll
                    for (int nt = 0; nt < 4; nt++)
                        MMA_TF32(acc[mt][nt], af[mt], bf[nt]);
            }
        }
        if (it + 1 < nk){
            unsigned* Ab = As + (cur ^ 1) * (BKK * LDA);
            unsigned* Bb = Bs + (cur ^ 1) * (BKK * LDB);
            Ab[(ak0+0)*LDA + ar0] = f2tf(a4[0].x); Ab[(ak0+1)*LDA + ar0] = f2tf(a4[0].y);
            Ab[(ak0+2)*LDA + ar0] = f2tf(a4[0].z); Ab[(ak0+3)*LDA + ar0] = f2tf(a4[0].w);
            Ab[(ak1+0)*LDA + ar1] = f2tf(a4[1].x); Ab[(ak1+1)*LDA + ar1] = f2tf(a4[1].y);
            Ab[(ak1+2)*LDA + ar1] = f2tf(a4[1].z); Ab[(ak1+3)*LDA + ar1] = f2tf(a4[1].w);
            Bb[br0*LDB + bc0+0] = f2tf(b4[0].x); Bb[br0*LDB + bc0+1] = f2tf(b4[0].y);
            Bb[br0*LDB + bc0+2] = f2tf(b4[0].z); Bb[br0*LDB + bc0+3] = f2tf(b4[0].w);
            Bb[br1*LDB + bc1+0] = f2tf(b4[1].x); Bb[br1*LDB + bc1+1] = f2tf(b4[1].y);
            Bb[br1*LDB + bc1+2] = f2tf(b4[1].z); Bb[br1*LDB + bc1+3] = f2tf(b4[1].w);
        }
        __syncthreads();
    }

    #pragma unroll
    for (int mt = 0; mt < 4; mt++){
        const int r0 = bm + wm + mt*16 + lr;
        #pragma unroll
        for (int nt = 0; nt < 4; nt++){
            const int c0 = bn + wn + nt*8 + 2*lc;
            const float bx = bias[c0], by = bias[c0+1];
            #pragma unroll
            for (int half = 0; half < 2; half++){
                const int r = r0 + half*8;
                float v0 = acc[mt][nt][half*2+0] + bx;
                float v1 = acc[mt][nt][half*2+1] + by;
                if (act){
                    v0 = 0.5f*v0*(1.f + erff(v0*0.70710678118654752f));
                    v1 = 0.5f*v1*(1.f + erff(v1*0.70710678118654752f));
                }
                if (resid){
                    v0 += resid[(size_t)r*N + c0];
                    v1 += resid[(size_t)r*N + c0+1];
                }
                *(float2*)&C[(size_t)r*N + c0] = make_float2(v0, v1);
            }
        }
    }
}

__global__ __launch_bounds__(256, 2) void tgemm_kernel(
    const float* __restrict__ A, const float* __restrict__ Bm,
    const float* __restrict__ bias, const float* __restrict__ resid,
    float* __restrict__ C, int N, int K, int act)
{
    __shared__ unsigned As[2*BKK*LDA];
    __shared__ unsigned Bs[2*BKK*LDB];
    gemm_body(A, Bm, bias, resid, C, N, K, act, As, Bs);
}

__global__ __launch_bounds__(256, 2) void qkv_kernel(
    const float* __restrict__ A,
    const float* __restrict__ Wq, const float* __restrict__ Wk, const float* __restrict__ Wv,
    const float* __restrict__ bq, const float* __restrict__ bk, const float* __restrict__ bv,
    float* __restrict__ oq, float* __restrict__ ok, float* __restrict__ ov)
{
    __shared__ unsigned As[2*BKK*LDA];
    __shared__ unsigned Bs[2*BKK*LDB];
    const int z = blockIdx.z;
    const float* Bm  = (z == 0) ? Wq : (z == 1) ? Wk : Wv;
    const float* bi  = (z == 0) ? bq : (z == 1) ? bk : bv;
    float*       Cm  = (z == 0) ? oq : (z == 1) ? ok : ov;
    gemm_body(A, Bm, bi, nullptr, Cm, EE, EE, 0, As, Bs);
}

// ================= FAVOR features via 3xTF32 MMA =================
__global__ __launch_bounds__(256) void feat_kernel(const float* __restrict__ proj, int l)
{
    __shared__ unsigned Ah[16*LDA], Al[16*LDA], Bh[16*LDB], Bl[16*LDB];
    __shared__ float diag[128];
    __shared__ unsigned rmax[128];
    __shared__ unsigned bmax;
    const int tid = threadIdx.x;
    const int c = blockIdx.x, bh = blockIdx.y;
    const int isq = (blockIdx.z == 0);
    const int b = bh / HH, h = bh % HH;
    const float* src = isq ? g_q : g_k;
    const int w = tid >> 5, lane = tid & 31;
    const int wm = (w & 1) * 64, wn = (w >> 1) * 32;
    const int lr = lane >> 2, lc = lane & 3;

    if (tid < 128) rmax[tid] = 0u;
    if (tid == 0) bmax = 0u;

    float acc[4][4][4];
    #pragma unroll
    for (int i = 0; i < 4; i++)
        #pragma unroll
        for (int j = 0; j < 4; j++)
            #pragma unroll
            for (int t = 0; t < 4; t++) acc[i][j][t] = 0.f;

    const int rrow = tid >> 1, kg = (tid & 1) * 8;
    float sq = 0.f;

    for (int kit = 0; kit < 4; kit++){
        const int k0 = kit * 16;
        #pragma unroll
        for (int q4 = 0; q4 < 2; q4++){
            float4 a = *(const float4*)&src[((size_t)(b*SS + c*128 + rrow))*EE + h*DHH + k0 + kg + q4*4];
            float vals[4] = {a.x*DNQ, a.y*DNQ, a.z*DNQ, a.w*DNQ};
            #pragma unroll
            for (int i = 0; i < 4; i++){
                sq += vals[i]*vals[i];
                unsigned hi, lo; tfsplit(vals[i], hi, lo);
                Ah[(kg + q4*4 + i)*LDA + rrow] = hi;
                Al[(kg + q4*4 + i)*LDA + rrow] = lo;
            }
        }
        #pragma unroll
        for (int q4 = 0; q4 < 2; q4++){
            float4 p = *(const float4*)&proj[rrow*DHH + k0 + kg + q4*4];
            float vals[4] = {p.x, p.y, p.z, p.w};
            #pragma unroll
            for (int i = 0; i < 4; i++){
                unsigned hi, lo; tfsplit(vals[i], hi, lo);
                Bh[(kg + q4*4 + i)*LDB + rrow] = hi;
                Bl[(kg + q4*4 + i)*LDB + rrow] = lo;
            }
        }
        __syncthreads();
        #pragma unroll
        for (int ks = 0; ks < 16; ks += 8){
            unsigned afh[4][4], afl[4][4], bfh[4][2], bfl[4][2];
            #pragma unroll
            for (int mt = 0; mt < 4; mt++){
                const int base = (ks + lc)*LDA + wm + mt*16 + lr;
                afh[mt][0] = Ah[base];        afl[mt][0] = Al[base];
                afh[mt][1] = Ah[base + 8];    afl[mt][1] = Al[base + 8];
                afh[mt][2] = Ah[base + 4*LDA];afl[mt][2] = Al[base + 4*LDA];
                afh[mt][3] = Ah[base + 4*LDA + 8]; afl[mt][3] = Al[base + 4*LDA + 8];
            }
            #pragma unroll
            for (int nt = 0; nt < 4; nt++){
                const int base = (ks + lc)*LDB + wn + nt*8 + lr;
                bfh[nt][0] = Bh[base];         bfl[nt][0] = Bl[base];
                bfh[nt][1] = Bh[base + 4*LDB]; bfl[nt][1] = Bl[base + 4*LDB];
            }
            #pragma unroll
            for (int mt = 0; mt < 4; mt++)
                #pragma unroll
                for (int nt = 0; nt < 4; nt++){
                    MMA_TF32(acc[mt][nt], afh[mt], bfh[nt]);
                    MMA_TF32(acc[mt][nt], afh[mt], bfl[nt]);
                    MMA_TF32(acc[mt][nt], afl[mt], bfh[nt]);
                }
        }
        __syncthreads();
    }
    {
        float other = __shfl_xor_sync(~0u, sq, 1);
        if ((tid & 1) == 0) diag[rrow] = 0.5f * (sq + other);
    }
    if (isq){
        #pragma unroll
        for (int mt = 0; mt < 4; mt++)
            #pragma unroll
            for (int half = 0; half < 2; half++){
                const int r = wm + mt*16 + lr + half*8;
                float m = -3.4e38f;
                #pragma unroll
                for (int nt = 0; nt < 4; nt++){
                    m = fmaxf(m, acc[mt][nt][half*2+0]);
                    m = fmaxf(m, acc[mt][nt][half*2+1]);
                }
                atomicMax(&rmax[r], f_enc(m));
            }
    } else {
        float m = -3.4e38f;
        #pragma unroll
        for (int mt = 0; mt < 4; mt++)
            #pragma unroll
            for (int nt = 0; nt < 4; nt++)
                #pragma unroll
                for (int t = 0; t < 4; t++) m = fmaxf(m, acc[mt][nt][t]);
        #pragma unroll
        for (int o = 16; o; o >>= 1) m = fmaxf(m, __shfl_xor_sync(~0u, m, o));
        if (lane == 0) atomicMax(&bmax, f_enc(m));
    }
    __syncthreads();

    const size_t qbase = (size_t)bh*SS + c*128;
    if (isq){
        #pragma unroll
        for (int mt = 0; mt < 4; mt++)
            #pragma unroll
            for (int half = 0; half < 2; half++){
                const int r = wm + mt*16 + lr + half*8;
                const float dg = diag[r], mx = f_dec(rmax[r]);
                #pragma unroll
                for (int nt = 0; nt < 4; nt++){
                    const int c0 = wn + nt*8 + 2*lc;
                    float v0 = RATIO*(expf(acc[mt][nt][half*2+0] - dg - mx) + KEPS);
                    float v1 = RATIO*(expf(acc[mt][nt][half*2+1] - dg - mx) + KEPS);
                    *(float2*)&g_qp[(qbase + r)*MMF + c0] = make_float2(v0, v1);
                }
            }
    } else {
        if (tid == 0) atomicMax(&g_kmaxv[l], bmax);
        #pragma unroll
        for (int mt = 0; mt < 4; mt++)
            #pragma unroll
            for (int half = 0; half < 2; half++){
                const int r = wm + mt*16 + lr + half*8;
                const float dg = diag[r];
                #pragma unroll
                for (int nt = 0; nt < 4; nt++){
                    const int c0 = wn + nt*8 + 2*lc;
                    float v0 = acc[mt][nt][half*2+0] - dg;
                    float v1 = acc[mt][nt][half*2+1] - dg;
                    *(float2*)&g_kp[(qbase + r)*MMF + c0] = make_float2(v0, v1);
                }
            }
    }
}

// fused: k features exp(global max) + per-chunk column sums zc
__global__ __launch_bounds__(128) void kfeat2zc_kernel(int l)
{
    const int c = blockIdx.x, bh = blockIdx.y, m = threadIdx.x;
    const size_t qbase = (size_t)bh*SS + c*128;
    const float gm = f_dec(g_kmaxv[l]);
    float s = 0.f;
    #pragma unroll 4
    for (int t = 0; t < 128; t++){
        size_t off = (qbase + t)*MMF + m;
        float v = RATIO * (expf(g_kp[off] - gm) + KEPS);
        g_kp[off] = v;
        s += v;
    }
    g_zc[(bh*NCH + c)*MMF + m] = s;
}

// ================= chunk Sc[m][d] = kp^T @ v via 3xTF32 =================
#define KVLDB 72
__global__ __launch_bounds__(256, 2) void chunk_kv_kernel()
{
    __shared__ unsigned Ah[16*LDA], Al[16*LDA], Bh[16*KVLDB], Bl[16*KVLDB];
    const int c = blockIdx.x, bh = blockIdx.y;
    const int b = bh / HH, h = bh % HH;
    const int tid = threadIdx.x;
    const int w = tid >> 5, lane = tid & 31;
    const int wm = (w & 1) * 64, wn = (w >> 1) * 16;
    const int lr = lane >> 2, lc = lane & 3;
    const size_t qbase = (size_t)bh*SS + c*128;

    float acc[4][2][4];
    #pragma unroll
    for (int i = 0; i < 4; i++)
        #pragma unroll
        for (int j = 0; j < 2; j++)
            #pragma unroll
            for (int t = 0; t < 4; t++) acc[i][j][t] = 0.f;

    const int at = tid >> 4, am0 = (tid & 15) * 8;
    const int bt = tid >> 4, bd0 = (tid & 15) * 4;

    for (int kit = 0; kit < 8; kit++){
        const int t0 = kit * 16;
        #pragma unroll
        for (int q4 = 0; q4 < 2; q4++){
            float4 a = *(const float4*)&g_kp[(qbase + t0 + at)*MMF + am0 + q4*4];
            float vals[4] = {a.x, a.y, a.z, a.w};
            #pragma unroll
            for (int i = 0; i < 4; i++){
                unsigned hi, lo; tfsplit(vals[i], hi, lo);
                Ah[at*LDA + am0 + q4*4 + i] = hi;
                Al[at*LDA + am0 + q4*4 + i] = lo;
            }
        }
        {
            float4 vv = *(const float4*)&g_v[((size_t)(b*SS + c*128 + t0 + bt))*EE + h*DHH + bd0];
            float vals[4] = {vv.x, vv.y, vv.z, vv.w};
            #pragma unroll
            for (int i = 0; i < 4; i++){
                unsigned hi, lo; tfsplit(vals[i], hi, lo);
                Bh[bt*KVLDB + bd0 + i] = hi;
                Bl[bt*KVLDB + bd0 + i] = lo;
            }
        }
        __syncthreads();
        #pragma unroll
        for (int ks = 0; ks < 16; ks += 8){
            unsigned afh[4][4], afl[4][4], bfh[2][2], bfl[2][2];
            #pragma unroll
            for (int mt = 0; mt < 4; mt++){
                const int base = (ks + lc)*LDA + wm + mt*16 + lr;
                afh[mt][0] = Ah[base];         afl[mt][0] = Al[base];
                afh[mt][1] = Ah[base + 8];     afl[mt][1] = Al[base + 8];
                afh[mt][2] = Ah[base + 4*LDA]; afl[mt][2] = Al[base + 4*LDA];
                afh[mt][3] = Ah[base + 4*LDA + 8]; afl[mt][3] = Al[base + 4*LDA + 8];
            }
            #pragma unroll
            for (int nt = 0; nt < 2; nt++){
                const int base = (ks + lc)*KVLDB + wn + nt*8 + lr;
                bfh[nt][0] = Bh[base];           bfl[nt][0] = Bl[base];
                bfh[nt][1] = Bh[base + 4*KVLDB]; bfl[nt][1] = Bl[base + 4*KVLDB];
            }
            #pragma unroll
            for (int mt = 0; mt < 4; mt++)
                #pragma unroll
                for (int nt = 0; nt < 2; nt++){
                    MMA_TF32(acc[mt][nt], afh[mt], bfh[nt]);
                    MMA_TF32(acc[mt][nt], afh[mt], bfl[nt]);
                    MMA_TF32(acc[mt][nt], afl[mt], bfh[nt]);
                }
        }
        __syncthreads();
    }
    const size_t base = ((size_t)(bh*NCH + c))*MMF;
    #pragma unroll
    for (int mt = 0; mt < 4; mt++)
        #pragma unroll
        for (int half = 0; half < 2; half++){
            const int m = wm + mt*16 + lr + half*8;
            #pragma unroll
            for (int nt = 0; nt < 2; nt++){
                const int d0 = wn + nt*8 + 2*lc;
                *(float2*)&g_Sc[(base + m)*DHH + d0] =
                    make_float2(acc[mt][nt][half*2+0], acc[mt][nt][half*2+1]);
            }
        }
}

// ---------------- parallel exclusive prefix over chunks ----------------
__global__ __launch_bounds__(1024) void chunk_prefix_kernel()
{
    const int bh = blockIdx.y;
    const int idx = blockIdx.x * 1024 + threadIdx.x;
    float run = 0.f;
    #pragma unroll
    for (int c = 0; c < NCH; c++){
        size_t off = ((size_t)(bh*NCH + c))*MMF*DHH + idx;
        float v = g_Sc[off];
        g_Sp[off] = run;
        run += v;
    }
    if (blockIdx.x == 0 && threadIdx.x < MMF){
        const int m = threadIdx.x;
        float rz = 0.f;
        #pragma unroll
        for (int c = 0; c < NCH; c++){
            int zb = (bh*NCH + c)*MMF + m;
            g_zp[zb] = rz;
            rz += g_zc[zb];
        }
    }
}

// ================= P = mask(qp @ kp^T) via 3xTF32 =================
__global__ __launch_bounds__(256) void chunk_p_kernel()
{
    __shared__ unsigned Ah[16*LDA], Al[16*LDA], Bh[16*LDB], Bl[16*LDB];
    const int c = blockIdx.x, bh = blockIdx.y;
    const int tid = threadIdx.x;
    const int w = tid >> 5, lane = tid & 31;
    const int wm = (w & 1) * 64, wn = (w >> 1) * 32;
    const int lr = lane >> 2, lc = lane & 3;
    const size_t qbase = (size_t)bh*SS + c*128;

    float acc[4][4][4];
    #pragma unroll
    for (int i = 0; i < 4; i++)
        #pragma unroll
        for (int j = 0; j < 4; j++)
            #pragma unroll
            for (int t = 0; t < 4; t++) acc[i][j][t] = 0.f;

    const int rrow = tid >> 1, kg = (tid & 1) * 8;

    for (int kit = 0; kit < 8; kit++){
        const int m0 = kit * 16;
        #pragma unroll
        for (int q4 = 0; q4 < 2; q4++){
            float4 a = *(const float4*)&g_qp[(qbase + rrow)*MMF + m0 + kg + q4*4];
            float va[4] = {a.x, a.y, a.z, a.w};
            float4 bk = *(const float4*)&g_kp[(qbase + rrow)*MMF + m0 + kg + q4*4];
            float vb[4] = {bk.x, bk.y, bk.z, bk.w};
            #pragma unroll
            for (int i = 0; i < 4; i++){
                unsigned hi, lo;
                tfsplit(va[i], hi, lo);
                Ah[(kg + q4*4 + i)*LDA + rrow] = hi;
                Al[(kg + q4*4 + i)*LDA + rrow] = lo;
                tfsplit(vb[i], hi, lo);
                Bh[(kg + q4*4 + i)*LDB + rrow] = hi;
                Bl[(kg + q4*4 + i)*LDB + rrow] = lo;
            }
        }
        __syncthreads();
        #pragma unroll
        for (int ks = 0; ks < 16; ks += 8){
            unsigned afh[4][4], afl[4][4], bfh[4][2], bfl[4][2];
            #pragma unroll
            for (int mt = 0; mt < 4; mt++){
                const int base = (ks + lc)*LDA + wm + mt*16 + lr;
                afh[mt][0] = Ah[base];         afl[mt][0] = Al[base];
                afh[mt][1] = Ah[base + 8];     afl[mt][1] = Al[base + 8];
                afh[mt][2] = Ah[base + 4*LDA]; afl[mt][2] = Al[base + 4*LDA];
                afh[mt][3] = Ah[base + 4*LDA + 8]; afl[mt][3] = Al[base + 4*LDA + 8];
            }
            #pragma unroll
            for (int nt = 0; nt < 4; nt++){
                const int base = (ks + lc)*LDB + wn + nt*8 + lr;
                bfh[nt][0] = Bh[base];         bfl[nt][0] = Bl[base];
                bfh[nt][1] = Bh[base + 4*LDB]; bfl[nt][1] = Bl[base + 4*LDB];
            }
            #pragma unroll
            for (int mt = 0; mt < 4; mt++)
                #pragma unroll
                for (int nt = 0; nt < 4; nt++){
                    MMA_TF32(acc[mt][nt], afh[mt], bfh[nt]);
                    MMA_TF32(acc[mt][nt], afh[mt], bfl[nt]);
                    MMA_TF32(acc[mt][nt], afl[mt], bfh[nt]);
                }
        }
        __syncthreads();
    }
    const size_t pbase = ((size_t)(bh*NCH + c))*128;
    #pragma unroll
    for (int mt = 0; mt < 4; mt++)
        #pragma unroll
        for (int half = 0; half < 2; half++){
            const int r = wm + mt*16 + lr + half*8;
            #pragma unroll
            for (int nt = 0; nt < 4; nt++){
                const int c0 = wn + nt*8 + 2*lc;
                float v0 = (c0   <= r) ? acc[mt][nt][half*2+0] : 0.f;
                float v1 = (c0+1 <= r) ? acc[mt][nt][half*2+1] : 0.f;
                *(float2*)&g_P[(pbase + r)*128 + c0] = make_float2(v0, v1);
            }
        }
}

// ================= out = ([P|qp] @ [v;Sp]) / den, den fused in staging =================
__global__ __launch_bounds__(256, 2) void chunk_o_kernel()
{
    __shared__ unsigned Ah[16*LDA], Al[16*LDA], Bh[16*KVLDB], Bl[16*KVLDB];
    __shared__ float densh[128];
    const int c = blockIdx.x, bh = blockIdx.y;
    const int b = bh / HH, h = bh % HH;
    const int tid = threadIdx.x;
    const int w = tid >> 5, lane = tid & 31;
    const int wm = (w & 1) * 64, wn = (w >> 1) * 16;
    const int lr = lane >> 2, lc = lane & 3;
    const size_t pbase = ((size_t)(bh*NCH + c))*128;
    const size_t qbase = (size_t)bh*SS + c*128;
    const size_t sbase = ((size_t)(bh*NCH + c))*MMF;

    float acc[4][2][4];
    #pragma unroll
    for (int i = 0; i < 4; i++)
        #pragma unroll
        for (int j = 0; j < 2; j++)
            #pragma unroll
            for (int t = 0; t < 4; t++) acc[i][j][t] = 0.f;

    const int rrow = tid >> 1, kg = (tid & 1) * 8;
    const int bt = tid >> 4, bd0 = (tid & 15) * 4;
    float denp = 0.f;

    for (int kit = 0; kit < 16; kit++){
        const int j0 = kit * 16;
        #pragma unroll
        for (int q4 = 0; q4 < 2; q4++){
            float4 a;
            if (j0 < 128) a = *(const float4*)&g_P[(pbase + rrow)*128 + j0 + kg + q4*4];
            else          a = *(const float4*)&g_qp[(qbase + rrow)*MMF + (j0 - 128) + kg + q4*4];
            float vals[4] = {a.x, a.y, a.z, a.w};
            if (j0 < 128){
                denp += vals[0] + vals[1] + vals[2] + vals[3];
            } else {
                float4 zpv = *(const float4*)&g_zp[sbase + (j0 - 128) + kg + q4*4];
                denp += vals[0]*zpv.x + vals[1]*zpv.y + vals[2]*zpv.z + vals[3]*zpv.w;
            }
            #pragma unroll
            for (int i = 0; i < 4; i++){
                unsigned hi, lo; tfsplit(vals[i], hi, lo);
                Ah[(kg + q4*4 + i)*LDA + rrow] = hi;
                Al[(kg + q4*4 + i)*LDA + rrow] = lo;
            }
        }
        {
            float4 hv;
            if (j0 < 128) hv = *(const float4*)&g_v[((size_t)(b*SS + c*128 + j0 + bt))*EE + h*DHH + bd0];
            else          hv = *(const float4*)&g_Sp[(sbase + (j0 - 128) + bt)*DHH + bd0];
            float vals[4] = {hv.x, hv.y, hv.z, hv.w};
            #pragma unroll
            for (int i = 0; i < 4; i++){
                unsigned hi, lo; tfsplit(vals[i], hi, lo);
                Bh[bt*KVLDB + bd0 + i] = hi;
                Bl[bt*KVLDB + bd0 + i] = lo;
            }
        }
        __syncthreads();
        #pragma unroll
        for (int ks = 0; ks < 16; ks += 8){
            unsigned afh[4][4], afl[4][4], bfh[2][2], bfl[2][2];
            #pragma unroll
            for (int mt = 0; mt < 4; mt++){
                const int base = (ks + lc)*LDA + wm + mt*16 + lr;
                afh[mt][0] = Ah[base];         afl[mt][0] = Al[base];
                afh[mt][1] = Ah[base + 8];     afl[mt][1] = Al[base + 8];
                afh[mt][2] = Ah[base + 4*LDA]; afl[mt][2] = Al[base + 4*LDA];
                afh[mt][3] = Ah[base + 4*LDA + 8]; afl[mt][3] = Al[base + 4*LDA + 8];
            }
            #pragma unroll
            for (int nt = 0; nt < 2; nt++){
                const int base = (ks + lc)*KVLDB + wn + nt*8 + lr;
                bfh[nt][0] = Bh[base];           bfl[nt][0] = Bl[base];
                bfh[nt][1] = Bh[base + 4*KVLDB]; bfl[nt][1] = Bl[base + 4*KVLDB];
            }
            #pragma unroll
            for (int mt = 0; mt < 4; mt++)
                #pragma unroll
                for (int nt = 0; nt < 2; nt++){
                    MMA_TF32(acc[mt][nt], afh[mt], bfh[nt]);
                    MMA_TF32(acc[mt][nt], afh[mt], bfl[nt]);
                    MMA_TF32(acc[mt][nt], afl[mt], bfh[nt]);
                }
        }
        __syncthreads();
    }
    // combine den across the 2 staging threads per row
    denp += __shfl_xor_sync(~0u, denp, 1);
    if ((tid & 1) == 0) densh[rrow] = denp;
    __syncthreads();

    #pragma unroll
    for (int mt = 0; mt < 4; mt++)
        #pragma unroll
        for (int half = 0; half < 2; half++){
            const int r = wm + mt*16 + lr + half*8;
            const float dinv = 1.f / (densh[r] + DEPS);
            #pragma unroll
            for (int nt = 0; nt < 2; nt++){
                const int d0 = wn + nt*8 + 2*lc;
                *(float2*)&g_o[((size_t)(b*SS + c*128 + r))*EE + h*DHH + d0] =
                    make_float2(acc[mt][nt][half*2+0]*dinv, acc[mt][nt][half*2+1]*dinv);
            }
        }
}

// ---------------- head projection ----------------
__global__ __launch_bounds__(64) void head_kernel(const float* __restrict__ hw, float* __restrict__ out)
{
    __shared__ float xs[EE];
    const int r = blockIdx.x, t = threadIdx.x;
    ((float4*)xs)[t]      = ((const float4*)(g_x + (size_t)r*EE))[t];
    ((float4*)xs)[t + 64] = ((const float4*)(g_x + (size_t)r*EE))[t + 64];
    __syncthreads();
    if (t < NVOC){
        float acc = 0.f;
        #pragma unroll 8
        for (int k = 0; k < EE; k++) acc += xs[k] * hw[k*NVOC + t];
        out[(size_t)r*NVOC + t] = acc;
    }
}

// ---------------- host launch ----------------
extern "C" void kernel_launch(void* const* d_in, const int* in_sizes, int n_in,
                              void* d_out, int out_size)
{
    (void)in_sizes; (void)n_in; (void)out_size;
    const int*   value = (const int*)  d_in[0];
    const int*   depth = (const int*)  d_in[1];
    const int*   pos   = (const int*)  d_in[2];
    const float* proj  = (const float*)d_in[3];
    const float* sos   = (const float*)d_in[4];
    const float* tok   = (const float*)d_in[5];
    const float* dep   = (const float*)d_in[6];
    const float* spa   = (const float*)d_in[7];
    const float* ln1w  = (const float*)d_in[8];
    const float* ln1b  = (const float*)d_in[9];
    const float* Wq    = (const float*)d_in[10];
    const float* bq    = (const float*)d_in[11];
    const float* Wk    = (const float*)d_in[12];
    const float* bk    = (const float*)d_in[13];
    const float* Wv    = (const float*)d_in[14];
    const float* bv    = (const float*)d_in[15];
    const float* Wo    = (const float*)d_in[16];
    const float* bo    = (const float*)d_in[17];
    const float* ln2w  = (const float*)d_in[18];
    const float* ln2b  = (const float*)d_in[19];
    const float* W1    = (const float*)d_in[20];
    const float* b1    = (const float*)d_in[21];
    const float* W2    = (const float*)d_in[22];
    const float* b2    = (const float*)d_in[23];
    const float* hw    = (const float*)d_in[24];

    float *px, *ph, *pq, *pk, *pv, *po, *pff;
    cudaGetSymbolAddress((void**)&px,  g_x);
    cudaGetSymbolAddress((void**)&ph,  g_h);
    cudaGetSymbolAddress((void**)&pq,  g_q);
    cudaGetSymbolAddress((void**)&pk,  g_k);
    cudaGetSymbolAddress((void**)&pv,  g_v);
    cudaGetSymbolAddress((void**)&po,  g_o);
    cudaGetSymbolAddress((void**)&pff, g_ff);

    embed_kernel<<<(BSR*EE + 255)/256, 256>>>(value, depth, pos, sos, tok, dep, spa);

    dim3 g512(4, 32);
    dim3 g2048(16, 32);
    dim3 gqkv(4, 32, 3);
    dim3 gfeat(NCH, BHH, 2);
    dim3 gchunk(NCH, BHH);
    dim3 gprefix(8, BHH);

    for (int l = 0; l < LL; l++){
        const float* prj = proj + (size_t)l*MMF*DHH;
        ln_kernel<<<BSR, 128>>>(px, ph, ln1w + l*EE, ln1b + l*EE);
        qkv_kernel<<<gqkv, 256>>>(ph,
            Wq + (size_t)l*EE*EE, Wk + (size_t)l*EE*EE, Wv + (size_t)l*EE*EE,
            bq + l*EE, bk + l*EE, bv + l*EE,
            pq, pk, pv);

        feat_kernel<<<gfeat, 256>>>(prj, l);
        kfeat2zc_kernel<<<gchunk, 128>>>(l);

        chunk_kv_kernel<<<gchunk, 256>>>();
        chunk_prefix_kernel<<<gprefix, 1024>>>();
        chunk_p_kernel<<<gchunk, 256>>>();
        chunk_o_kernel<<<gchunk, 256>>>();

        tgemm_kernel<<<g512, 256>>>(po, Wo + (size_t)l*EE*EE, bo + l*EE, px, px, EE, EE, 0);
        ln_kernel<<<BSR, 128>>>(px, ph, ln2w + l*EE, ln2b + l*EE);
        tgemm_kernel<<<g2048, 256>>>(ph, W1 + (size_t)l*EE*FFD, b1 + l*FFD, nullptr, pff, FFD, EE, 1);
        tgemm_kernel<<<g512, 256>>>(pff, W2 + (size_t)l*FFD*EE, b2 + l*EE, px, px, EE, FFD, 0);
    }

    head_kernel<<<BSR, 64>>>(hw, (float*)d_out);
}